// round 8
// baseline (speedup 1.0000x reference)
#include <cuda_runtime.h>
#include <cuda_bf16.h>
#include <math.h>
#include <stdint.h>

// ---------------------------------------------------------------------------
// GraphDecoder on tensor cores (mma.sync bf16, 3-term hi/lo split, fp32 acc).
// Round 8:
//  - tile_mma reordered term-outermost (no back-to-back accumulator RAW)
//  - single __syncthreads per K-chunk (issue(s+2) after barrier; 3-stage ring)
//  - relation kernel: A ring 3 buffers, B ring 3 stages, single sync,
//    98KB smem -> keeps 2 CTAs/SM on the 1024-CTA grid
// ---------------------------------------------------------------------------

#define LL  8
#define SS  128
#define DD  512
#define HH  8
#define HDD 64
#define NT  1024

typedef __nv_bfloat16 bf16;

// ---- persistent scratch ----------------------------------------------------
#define OFF_AIW 0            // 3 x 786432
#define OFF_AOW 2359296      // 3 x 262144
#define OFF_F1W 3145728      // 3 x 1048576
#define OFF_F2W 6291456      // 3 x 1048576
#define OFF_W0  9437184      // 4 x 262144
#define OFF_W1  10485760
#define OFF_W2  11534336
#define WTOT    12582912

#define PSTR  (NT * DD)           // 524288 floats per partial slab
#define QPSTR (NT * 3 * DD)       // qkv partial stride

__device__ bf16  g_wh[WTOT], g_wl[WTOT];
__device__ bf16  g_s0h[4 * NT * DD], g_s0l[4 * NT * DD];
__device__ bf16  g_s1h[4 * NT * DD], g_s1l[4 * NT * DD];
__device__ float g_h[NT * DD];
__device__ float g_qkv[2 * NT * 3 * DD];   // 2 split-K partials
__device__ float g_part[8 * NT * DD];      // split-K partial arena
__device__ float g_Wv[NT * DD];
__device__ float g_sub[NT * DD];

// ========================= low-level helpers ================================
__device__ __forceinline__ uint32_t smem_u32(const void* p) {
    uint32_t a;
    asm("{ .reg .u64 t; cvta.to.shared.u64 t, %1; cvt.u32.u64 %0, t; }"
        : "=r"(a) : "l"(p));
    return a;
}

// swizzle for 64-byte rows: XOR bits [4:6) with bits [7:9)
__device__ __forceinline__ uint32_t swz(uint32_t off) {
    return off ^ (((off >> 7) & 3u) << 4);
}

__device__ __forceinline__ void ldmx4(uint32_t* r, uint32_t addr) {
    asm volatile("ldmatrix.sync.aligned.m8n8.x4.shared.b16 {%0,%1,%2,%3}, [%4];"
        : "=r"(r[0]), "=r"(r[1]), "=r"(r[2]), "=r"(r[3]) : "r"(addr));
}

__device__ __forceinline__ void mma16816(float* d, const uint32_t* a,
                                         const uint32_t* b) {
    asm volatile(
        "mma.sync.aligned.m16n8k16.row.col.f32.bf16.bf16.f32 "
        "{%0,%1,%2,%3}, {%4,%5,%6,%7}, {%8,%9}, {%0,%1,%2,%3};"
        : "+f"(d[0]), "+f"(d[1]), "+f"(d[2]), "+f"(d[3])
        : "r"(a[0]), "r"(a[1]), "r"(a[2]), "r"(a[3]), "r"(b[0]), "r"(b[1]));
}

__device__ __forceinline__ void cp16(uint32_t smem, const void* g) {
    asm volatile("cp.async.cg.shared.global [%0], [%1], 16;"
        :: "r"(smem), "l"(g));
}
#define CP_COMMIT asm volatile("cp.async.commit_group;" ::: "memory")
#define CP_WAIT1  asm volatile("cp.async.wait_group 1;" ::: "memory")

__device__ __forceinline__ void split2(float x, float y, uint32_t& hi, uint32_t& lo) {
    __nv_bfloat162 h, l;
    h.x = __float2bfloat16(x); h.y = __float2bfloat16(y);
    l.x = __float2bfloat16(x - __bfloat162float(h.x));
    l.y = __float2bfloat16(y - __bfloat162float(h.y));
    hi = *(uint32_t*)&h; lo = *(uint32_t*)&l;
}

#define TILE_B 8192   // one 128x32 bf16 tile, 64B rows, swizzled

// 128x128-tile mma over one 32-wide K slab (hi/lo 3-term).
// Term-outermost: each accumulator reused only every 8 MMAs (no RAW chains).
__device__ __forceinline__ void tile_mma(
    uint32_t ahB, uint32_t alB, uint32_t bhB, uint32_t blB,
    const uint32_t* a0, const uint32_t* a1, const uint32_t (*bo)[2],
    float (&acc)[2][8][4])
{
#pragma unroll
    for (int kk = 0; kk < 2; ++kk) {
        uint32_t ah[2][4], al[2][4];
        ldmx4(ah[0], ahB + a0[kk]);
        ldmx4(ah[1], ahB + a1[kk]);
        ldmx4(al[0], alB + a0[kk]);
        ldmx4(al[1], alB + a1[kk]);
#pragma unroll
        for (int hf = 0; hf < 2; ++hf) {
            uint32_t bh[4][2], bl[4][2];
#pragma unroll
            for (int ng = 0; ng < 2; ++ng) {
                uint32_t r[4];
                ldmx4(r, bhB + bo[2 * hf + ng][kk]);
                bh[2*ng][0] = r[0]; bh[2*ng][1] = r[1];
                bh[2*ng+1][0] = r[2]; bh[2*ng+1][1] = r[3];
                ldmx4(r, blB + bo[2 * hf + ng][kk]);
                bl[2*ng][0] = r[0]; bl[2*ng][1] = r[1];
                bl[2*ng+1][0] = r[2]; bl[2*ng+1][1] = r[3];
            }
            // term 1: ah*bh
#pragma unroll
            for (int mt = 0; mt < 2; ++mt)
#pragma unroll
                for (int nt = 0; nt < 4; ++nt)
                    mma16816(acc[mt][4*hf + nt], ah[mt], bh[nt]);
            // term 2: ah*bl
#pragma unroll
            for (int mt = 0; mt < 2; ++mt)
#pragma unroll
                for (int nt = 0; nt < 4; ++nt)
                    mma16816(acc[mt][4*hf + nt], ah[mt], bl[nt]);
            // term 3: al*bh
#pragma unroll
            for (int mt = 0; mt < 2; ++mt)
#pragma unroll
                for (int nt = 0; nt < 4; ++nt)
                    mma16816(acc[mt][4*hf + nt], al[mt], bh[nt]);
        }
    }
}

// ---------------------------------------------------------------------------
// bf16 GEMM, batched (z) + split-K (ks). C[z] = act(A[z] @ Wt[z]^T + bias[z]).
// ks>1: fp32 partials at Cf + z*zsC + kz*pstr; bias only on kz==0; no relu.
// 128x128 tile, BK=32, 3-stage ring, ONE __syncthreads per chunk, 2 CTAs/SM.
// ---------------------------------------------------------------------------
#define STAGE_BYTES (4 * TILE_B)        // 32768: Ah,Al,Bh,Bl
#define GEMM_SMEM   (3 * STAGE_BYTES + 128)   // 98432

__global__ void __launch_bounds__(256, 2) gemm_bf16_kernel(
    const bf16* __restrict__ Ah, const bf16* __restrict__ Al,
    const bf16* __restrict__ Wh, const bf16* __restrict__ Wl,
    const float* __restrict__ bias,
    float* __restrict__ Cf, bf16* __restrict__ Ch, bf16* __restrict__ Cl,
    int N, int K, int relu, int ks, int pstr,
    int zsA, int zsW, int zsB, int zsC)
{
    extern __shared__ char smch[];
    const uint32_t base = (smem_u32(smch) + 127) & ~127u;

    const int z  = blockIdx.z / ks;
    const int kz = blockIdx.z % ks;
    const int Klocal = K / ks;
    const int kbase = kz * Klocal;

    Ah += (size_t)z * zsA;  Al += (size_t)z * zsA;
    Wh += (size_t)z * zsW;  Wl += (size_t)z * zsW;
    bias += (size_t)z * zsB;
    if (Cf) Cf += (size_t)z * zsC + (size_t)kz * pstr;
    if (Ch) { Ch += (size_t)z * zsC; Cl += (size_t)z * zsC; }

    const int tid  = threadIdx.x;
    const int lane = tid & 31;
    const int wid  = tid >> 5;
    const int wm   = wid & 3;
    const int wn   = wid >> 2;
    const int m0 = blockIdx.y * 128;
    const int n0 = blockIdx.x * 128;

    // per-thread cp.async descriptors: 8 x 16B chunks per stage
    const bf16* gsrc[8];
    uint32_t sdst[8];
#pragma unroll
    for (int it = 0; it < 8; ++it) {
        int c = tid + it * 256;
        int a = c >> 9, idx = c & 511, row = idx >> 2, q = idx & 3;
        const bf16* p;
        if (a == 0)      p = Ah + (size_t)(m0 + row) * K;
        else if (a == 1) p = Al + (size_t)(m0 + row) * K;
        else if (a == 2) p = Wh + (size_t)(n0 + row) * K;
        else             p = Wl + (size_t)(n0 + row) * K;
        gsrc[it] = p + kbase + q * 8;
        sdst[it] = a * TILE_B + swz(row * 64 + q * 16);
    }

    const int nch = Klocal >> 5;
    auto issue = [&](int s) {
        uint32_t st = base + (s % 3) * STAGE_BYTES;
#pragma unroll
        for (int it = 0; it < 8; ++it)
            cp16(st + sdst[it], gsrc[it] + s * 32);
    };
    issue(0); CP_COMMIT;
    issue(1); CP_COMMIT;

    const int aRow = wm * 32 + (lane & 15);
    const int aCol = (lane >> 4) * 8;
    const int bRow = wn * 64 + (lane & 7) + ((lane >> 4) << 3);
    const int bCol = ((lane >> 3) & 1) * 8;
    uint32_t a0[2], a1[2], bo[4][2];
#pragma unroll
    for (int kk = 0; kk < 2; ++kk) {
        a0[kk] = swz(aRow * 64 + aCol * 2 + kk * 32);
        a1[kk] = swz((aRow + 16) * 64 + aCol * 2 + kk * 32);
#pragma unroll
        for (int ng = 0; ng < 4; ++ng)
            bo[ng][kk] = swz((bRow + ng * 16) * 64 + bCol * 2 + kk * 32);
    }

    float acc[2][8][4] = {};

    for (int s = 0; s < nch; ++s) {
        CP_WAIT1;                 // stage s arrived (s+1 may be pending)
        __syncthreads();          // all warps done computing stage s-1
        if (s + 2 < nch) issue(s + 2);   // -> buffer (s-1)%3, drained above
        CP_COMMIT;
        uint32_t st = base + (s % 3) * STAGE_BYTES;
        tile_mma(st, st + TILE_B, st + 2 * TILE_B, st + 3 * TILE_B,
                 a0, a1, bo, acc);
    }

    const int addb = (kz == 0);
#pragma unroll
    for (int mt = 0; mt < 2; ++mt) {
        int r0 = m0 + wm * 32 + mt * 16 + (lane >> 2);
#pragma unroll
        for (int nt = 0; nt < 8; ++nt) {
            int col = n0 + wn * 64 + nt * 8 + (lane & 3) * 2;
            float b0 = addb ? bias[col] : 0.f, b1 = addb ? bias[col + 1] : 0.f;
            float v0 = acc[mt][nt][0] + b0, v1 = acc[mt][nt][1] + b1;
            float v2 = acc[mt][nt][2] + b0, v3 = acc[mt][nt][3] + b1;
            if (relu) {
                v0 = fmaxf(v0, 0.f); v1 = fmaxf(v1, 0.f);
                v2 = fmaxf(v2, 0.f); v3 = fmaxf(v3, 0.f);
            }
            if (Ch) {
                uint32_t hh, ll;
                split2(v0, v1, hh, ll);
                *(uint32_t*)&Ch[(size_t)r0 * N + col] = hh;
                *(uint32_t*)&Cl[(size_t)r0 * N + col] = ll;
                split2(v2, v3, hh, ll);
                *(uint32_t*)&Ch[(size_t)(r0 + 8) * N + col] = hh;
                *(uint32_t*)&Cl[(size_t)(r0 + 8) * N + col] = ll;
            } else {
                *(float2*)&Cf[(size_t)r0 * N + col]       = make_float2(v0, v1);
                *(float2*)&Cf[(size_t)(r0 + 8) * N + col] = make_float2(v2, v3);
            }
        }
    }
}

// ---------------------------------------------------------------------------
// Relation tensor: per block (b,i): out[b,i,:,:] = ((sub_b * W_bi) @ obj_b^T)
// A: fp32 load + scale + split, 3-buffer ring; B: 3-stage cp.async ring.
// ONE __syncthreads per chunk; 98KB smem -> 2 CTAs/SM.
// ---------------------------------------------------------------------------
#define RA_STAGE (2 * TILE_B)   // Ah, Al
#define RB_STAGE (2 * TILE_B)   // Bh, Bl
#define REL_SMEM (2048 + 3 * RA_STAGE + 3 * RB_STAGE + 128)  // 100480

__global__ void __launch_bounds__(256, 2) final_tc_kernel(
    const float* __restrict__ sub, const bf16* __restrict__ objh,
    const bf16* __restrict__ objl, const float* __restrict__ Wv,
    float* __restrict__ out)
{
    extern __shared__ char smch[];
    const uint32_t sb = (smem_u32(smch) + 127) & ~127u;
    float* ws = (float*)(smch + (sb - smem_u32(smch)));
    char* aPtr = (char*)ws + 2048;
    const uint32_t aBase = sb + 2048;
    const uint32_t bBase = aBase + 3 * RA_STAGE;

    const int i = blockIdx.x;
    const int b = blockIdx.y;
    const int tid  = threadIdx.x;
    const int lane = tid & 31;
    const int wid  = tid >> 5;
    const int wm   = wid & 3;
    const int wn   = wid >> 2;

    const float* wrow = Wv + (size_t)(b * SS + i) * DD;
    ws[tid]       = wrow[tid];
    ws[tid + 256] = wrow[tid + 256];

    const float* subB = sub + (size_t)b * SS * DD;
    const bf16* ohB = objh + (size_t)b * SS * DD;
    const bf16* olB = objl + (size_t)b * SS * DD;

    const bf16* bsrc[4];
    uint32_t bdst[4];
#pragma unroll
    for (int it = 0; it < 4; ++it) {
        int c = tid + it * 256;
        int a = c >> 9, idx = c & 511, row = idx >> 2, q = idx & 3;
        bsrc[it] = (a ? olB : ohB) + (size_t)row * DD + q * 8;
        bdst[it] = a * TILE_B + swz(row * 64 + q * 16);
    }
    int aLrow[4], aLc4[4];
#pragma unroll
    for (int it = 0; it < 4; ++it) {
        int idx = tid + it * 256;
        aLrow[it] = idx >> 3;
        aLc4[it]  = (idx & 7) << 2;
    }

    auto issueB = [&](int s) {
        uint32_t st = bBase + (s % 3) * RB_STAGE;
#pragma unroll
        for (int it = 0; it < 4; ++it)
            cp16(st + bdst[it], bsrc[it] + s * 32);
    };
    auto loadA = [&](int s, float4* r) {
#pragma unroll
        for (int it = 0; it < 4; ++it)
            r[it] = *(const float4*)&subB[(size_t)aLrow[it] * DD + s * 32 + aLc4[it]];
    };
    auto storeA = [&](int s, const float4* r) {
        char* dh = aPtr + (s % 3) * RA_STAGE;
        int kc = s * 32;
#pragma unroll
        for (int it = 0; it < 4; ++it) {
            float4 v = r[it];
            v.x *= ws[kc + aLc4[it]];     v.y *= ws[kc + aLc4[it] + 1];
            v.z *= ws[kc + aLc4[it] + 2]; v.w *= ws[kc + aLc4[it] + 3];
            uint32_t h0, h1, l0, l1;
            split2(v.x, v.y, h0, l0);
            split2(v.z, v.w, h1, l1);
            uint32_t off = swz(aLrow[it] * 64 + aLc4[it] * 2);
            *(uint2*)(dh + off)          = make_uint2(h0, h1);
            *(uint2*)(dh + TILE_B + off) = make_uint2(l0, l1);
        }
    };

    issueB(0); CP_COMMIT;
    issueB(1); CP_COMMIT;
    __syncthreads();              // ws visible
    {
        float4 r0[4];
        loadA(0, r0);
        storeA(0, r0);
    }

    const int aRow = wm * 32 + (lane & 15);
    const int aCol = (lane >> 4) * 8;
    const int bRow = wn * 64 + (lane & 7) + ((lane >> 4) << 3);
    const int bCol = ((lane >> 3) & 1) * 8;
    uint32_t a0[2], a1[2], bo[4][2];
#pragma unroll
    for (int kk = 0; kk < 2; ++kk) {
        a0[kk] = swz(aRow * 64 + aCol * 2 + kk * 32);
        a1[kk] = swz((aRow + 16) * 64 + aCol * 2 + kk * 32);
#pragma unroll
        for (int ng = 0; ng < 4; ++ng)
            bo[ng][kk] = swz((bRow + ng * 16) * 64 + bCol * 2 + kk * 32);
    }

    float acc[2][8][4] = {};
    float4 pre[4];
    loadA(1, pre);

    for (int s = 0; s < 16; ++s) {
        CP_WAIT1;                 // B stage s arrived
        __syncthreads();          // compute(s-1) done by all warps;
                                  // also publishes storeA(s) smem writes
        if (s + 1 < 16) storeA(s + 1, pre);   // A buf (s+1)%3: read at s-2, done
        if (s + 2 < 16) issueB(s + 2);        // B buf (s-1)%3: read at s-1, done
        CP_COMMIT;
        if (s + 2 < 16) loadA(s + 2, pre);
        uint32_t aB = aBase + (s % 3) * RA_STAGE;
        uint32_t bB = bBase + (s % 3) * RB_STAGE;
        tile_mma(aB, aB + TILE_B, bB, bB + TILE_B, a0, a1, bo, acc);
    }
    // NOTE: storeA(s+1) runs before compute(s); consumers of storeA(s+1)
    // (compute at iter s+1) pass another __syncthreads first — visible.

    float* outB = out + (size_t)(b * SS + i) * SS * SS;
#pragma unroll
    for (int mt = 0; mt < 2; ++mt) {
        int r0 = wm * 32 + mt * 16 + (lane >> 2);
#pragma unroll
        for (int nt = 0; nt < 8; ++nt) {
            int col = wn * 64 + nt * 8 + (lane & 3) * 2;
            *(float2*)&outB[(size_t)r0 * SS + col] =
                make_float2(acc[mt][nt][0], acc[mt][nt][1]);
            *(float2*)&outB[(size_t)(r0 + 8) * SS + col] =
                make_float2(acc[mt][nt][2], acc[mt][nt][3]);
        }
    }
}

// ---------------------------------------------------------------------------
// Attention over axis L per (s, h); sums 2 qkv split-K partials; bf16 hi/lo out.
// ---------------------------------------------------------------------------
__global__ void attn_kernel(const float* __restrict__ qkv,
                            bf16* __restrict__ oh, bf16* __restrict__ ol)
{
    const int s = blockIdx.x;
    const int h = blockIdx.y;
    const int t = threadIdx.x;  // 0..63

    __shared__ float qs[8][65], ks[8][65], vs[8][65];
    __shared__ float at[8][9];

#pragma unroll
    for (int l = 0; l < 8; ++l) {
        size_t base = (size_t)(l * SS + s) * (3 * DD) + h * HDD + t;
        qs[l][t] = qkv[base]          + qkv[base + QPSTR];
        ks[l][t] = qkv[base + DD]     + qkv[base + DD + QPSTR];
        vs[l][t] = qkv[base + 2 * DD] + qkv[base + 2 * DD + QPSTR];
    }
    __syncthreads();

    const int l = t >> 3;
    const int m = t & 7;
    float sc = 0.0f;
#pragma unroll
    for (int d = 0; d < HDD; ++d) sc += qs[l][d] * ks[m][d];
    sc *= 0.125f;

    float mx = sc;
#pragma unroll
    for (int off = 1; off < 8; off <<= 1)
        mx = fmaxf(mx, __shfl_xor_sync(0xffffffffu, mx, off));
    float e = __expf(sc - mx);
    float sm = e;
#pragma unroll
    for (int off = 1; off < 8; off <<= 1)
        sm += __shfl_xor_sync(0xffffffffu, sm, off);
    at[l][m] = e / sm;
    __syncthreads();

    const int dg = (t & 7) * 8;
    float accv[8] = {};
#pragma unroll
    for (int mm = 0; mm < 8; ++mm) {
        float a = at[l][mm];
#pragma unroll
        for (int j = 0; j < 8; ++j)
            accv[j] = fmaf(a, vs[mm][dg + j], accv[j]);
    }
    size_t ob = (size_t)(l * SS + s) * DD + h * HDD + dg;
#pragma unroll
    for (int j = 0; j < 8; j += 2) {
        uint32_t hh, ll;
        split2(accv[j], accv[j + 1], hh, ll);
        *(uint32_t*)&oh[ob + j] = hh;
        *(uint32_t*)&ol[ob + j] = ll;
    }
}

// ---------------------------------------------------------------------------
// out = LayerNorm(a + sum_{p<np} P[p*pstr + .]); emits bf16 hi/lo if outh.
// ---------------------------------------------------------------------------
__global__ void add_ln_kernel(const float* __restrict__ a,
                              const float* __restrict__ P, int np, int pstr,
                              const float* __restrict__ gam, const float* __restrict__ bet,
                              float* __restrict__ out,
                              bf16* __restrict__ outh, bf16* __restrict__ outl)
{
    const int row = blockIdx.x;
    const int t = threadIdx.x;
    const size_t base = (size_t)row * DD;
    const int c = 2 * t;

    float v0 = a[base + c];
    float v1 = a[base + c + 1];
    for (int p = 0; p < np; ++p) {
        v0 += P[(size_t)p * pstr + base + c];
        v1 += P[(size_t)p * pstr + base + c + 1];
    }

    float s = v0 + v1;
    float q = v0 * v0 + v1 * v1;

    __shared__ float sred[16];
#pragma unroll
    for (int off = 16; off > 0; off >>= 1) {
        s += __shfl_xor_sync(0xffffffffu, s, off);
        q += __shfl_xor_sync(0xffffffffu, q, off);
    }
    if ((t & 31) == 0) { sred[t >> 5] = s; sred[(t >> 5) + 8] = q; }
    __syncthreads();
    if (t < 32) {
        float ss = (t < 8) ? sred[t] : 0.0f;
        float qq = (t < 8) ? sred[t + 8] : 0.0f;
#pragma unroll
        for (int off = 4; off > 0; off >>= 1) {
            ss += __shfl_xor_sync(0xffffffffu, ss, off);
            qq += __shfl_xor_sync(0xffffffffu, qq, off);
        }
        if (t == 0) { sred[0] = ss; sred[1] = qq; }
    }
    __syncthreads();

    const float mean = sred[0] * (1.0f / 512.0f);
    const float var  = sred[1] * (1.0f / 512.0f) - mean * mean;
    const float rstd = rsqrtf(var + 1e-5f);

    float y0 = (v0 - mean) * rstd * gam[c]     + bet[c];
    float y1 = (v1 - mean) * rstd * gam[c + 1] + bet[c + 1];
    *(float2*)&out[base + c] = make_float2(y0, y1);
    if (outh) {
        uint32_t hh, ll;
        split2(y0, y1, hh, ll);
        *(uint32_t*)&outh[base + c] = hh;
        *(uint32_t*)&outl[base + c] = ll;
    }
}

// ---------------------------------------------------------------------------
// Fused splitter: 8 segments of fp32 -> bf16 hi/lo (one launch).
// ---------------------------------------------------------------------------
struct SplitArgs {
    const float* src[8];
    bf16* dh[8];
    bf16* dl[8];
    int bstart[9];
};

__global__ void fused_split_kernel(SplitArgs sa)
{
    int blk = blockIdx.x;
    int seg = 0;
#pragma unroll
    for (int s = 1; s < 8; ++s) seg += (blk >= sa.bstart[s]);
    int idx = (blk - sa.bstart[seg]) * 256 + threadIdx.x;
    float4 x = ((const float4*)sa.src[seg])[idx];
    uint32_t h0, h1, l0, l1;
    split2(x.x, x.y, h0, l0);
    split2(x.z, x.w, h1, l1);
    ((uint2*)sa.dh[seg])[idx] = make_uint2(h0, h1);
    ((uint2*)sa.dl[seg])[idx] = make_uint2(l0, l1);
}

// ---------------------------------------------------------------------------
// Consumes 8 mlp2 split-K2 partial slabs (z-major pairs):
//   sub = P0+P1; obj = P2+P3 -> bf16 hi/lo; Wv = (P4+P5)*(P6+P7).
// ---------------------------------------------------------------------------
__global__ void mul_split_kernel(const float* __restrict__ P,
                                 float* __restrict__ subS, float* __restrict__ Wv,
                                 bf16* __restrict__ oh, bf16* __restrict__ ol)
{
    int i = blockIdx.x * blockDim.x + threadIdx.x;   // float4 index
    const float4* P4 = (const float4*)P;
    const int S4 = PSTR / 4;

    float4 s0 = P4[i], s1 = P4[i + S4];
    ((float4*)subS)[i] = make_float4(s0.x + s1.x, s0.y + s1.y,
                                     s0.z + s1.z, s0.w + s1.w);

    float4 o0 = P4[i + 2 * S4], o1 = P4[i + 3 * S4];
    float ox = o0.x + o1.x, oy = o0.y + o1.y, oz = o0.z + o1.z, ow = o0.w + o1.w;
    uint32_t h0, h1, l0, l1;
    split2(ox, oy, h0, l0);
    split2(oz, ow, h1, l1);
    ((uint2*)oh)[i] = make_uint2(h0, h1);
    ((uint2*)ol)[i] = make_uint2(l0, l1);

    float4 a0 = P4[i + 4 * S4], a1 = P4[i + 5 * S4];
    float4 b0 = P4[i + 6 * S4], b1 = P4[i + 7 * S4];
    ((float4*)Wv)[i] = make_float4((a0.x + a1.x) * (b0.x + b1.x),
                                   (a0.y + a1.y) * (b0.y + b1.y),
                                   (a0.z + a1.z) * (b0.z + b1.z),
                                   (a0.w + a1.w) * (b0.w + b1.w));
}

// ---------------------------------------------------------------------------
extern "C" void kernel_launch(void* const* d_in, const int* in_sizes, int n_in,
                              void* d_out, int out_size)
{
    const float* x   = (const float*)d_in[0];
    const float* aiw = (const float*)d_in[1];
    const float* aib = (const float*)d_in[2];
    const float* aow = (const float*)d_in[3];
    const float* aob = (const float*)d_in[4];
    const float* l1w = (const float*)d_in[5];
    const float* l1b = (const float*)d_in[6];
    const float* l2w = (const float*)d_in[7];
    const float* l2b = (const float*)d_in[8];
    const float* f1w = (const float*)d_in[9];
    const float* f1b = (const float*)d_in[10];
    const float* f2w = (const float*)d_in[11];
    const float* f2b = (const float*)d_in[12];
    const float* flw = (const float*)d_in[13];
    const float* flb = (const float*)d_in[14];
    const float* w0  = (const float*)d_in[15];
    const float* b0  = (const float*)d_in[16];
    const float* w1  = (const float*)d_in[17];
    const float* b1  = (const float*)d_in[18];
    const float* w2  = (const float*)d_in[19];
    const float* b2  = (const float*)d_in[20];
    float* out = (float*)d_out;

    bf16 *wh, *wl, *s0h, *s0l, *s1h, *s1l;
    float *h, *qkv, *part, *Wv, *subS;
    cudaGetSymbolAddress((void**)&wh,   g_wh);
    cudaGetSymbolAddress((void**)&wl,   g_wl);
    cudaGetSymbolAddress((void**)&s0h,  g_s0h);
    cudaGetSymbolAddress((void**)&s0l,  g_s0l);
    cudaGetSymbolAddress((void**)&s1h,  g_s1h);
    cudaGetSymbolAddress((void**)&s1l,  g_s1l);
    cudaGetSymbolAddress((void**)&h,    g_h);
    cudaGetSymbolAddress((void**)&qkv,  g_qkv);
    cudaGetSymbolAddress((void**)&part, g_part);
    cudaGetSymbolAddress((void**)&Wv,   g_Wv);
    cudaGetSymbolAddress((void**)&subS, g_sub);

    cudaFuncSetAttribute(gemm_bf16_kernel,
                         cudaFuncAttributeMaxDynamicSharedMemorySize, GEMM_SMEM);
    cudaFuncSetAttribute(final_tc_kernel,
                         cudaFuncAttributeMaxDynamicSharedMemorySize, REL_SMEM);

    // ---- launch 1: all splits fused (weights + x) ----
    {
        SplitArgs sa;
        sa.src[0] = aiw; sa.dh[0] = wh + OFF_AIW; sa.dl[0] = wl + OFF_AIW;
        sa.src[1] = aow; sa.dh[1] = wh + OFF_AOW; sa.dl[1] = wl + OFF_AOW;
        sa.src[2] = f1w; sa.dh[2] = wh + OFF_F1W; sa.dl[2] = wl + OFF_F1W;
        sa.src[3] = f2w; sa.dh[3] = wh + OFF_F2W; sa.dl[3] = wl + OFF_F2W;
        sa.src[4] = w0;  sa.dh[4] = wh + OFF_W0;  sa.dl[4] = wl + OFF_W0;
        sa.src[5] = w1;  sa.dh[5] = wh + OFF_W1;  sa.dl[5] = wl + OFF_W1;
        sa.src[6] = w2;  sa.dh[6] = wh + OFF_W2;  sa.dl[6] = wl + OFF_W2;
        sa.src[7] = x;   sa.dh[7] = s0h;          sa.dl[7] = s0l;
        int sizes[8] = {2359296, 786432, 3145728, 3145728,
                        1048576, 1048576, 1048576, 524288};
        int acc = 0;
        for (int s = 0; s < 8; ++s) { sa.bstart[s] = acc; acc += sizes[s] / 1024; }
        sa.bstart[8] = acc;
        fused_split_kernel<<<acc, 256>>>(sa);
    }

    // ---- encoder: 3 post-norm layers ----
    for (int i = 0; i < 3; ++i) {
        // qkv, split-K2 -> 2 partials in g_qkv
        gemm_bf16_kernel<<<dim3(12, 8, 2), 256, GEMM_SMEM>>>(
            s0h, s0l, wh + OFF_AIW + (size_t)i * 786432, wl + OFF_AIW + (size_t)i * 786432,
            aib + i * 1536, qkv, nullptr, nullptr, 1536, 512, 0, 2, QPSTR, 0, 0, 0, 0);

        attn_kernel<<<dim3(SS, HH), 64>>>(qkv, s1h, s1l);

        // attn-out, split-K4 (launch 4 on i=0: ncu slot)
        gemm_bf16_kernel<<<dim3(4, 8, 4), 256, GEMM_SMEM>>>(
            s1h, s1l, wh + OFF_AOW + (size_t)i * 262144, wl + OFF_AOW + (size_t)i * 262144,
            aob + i * 512, part, nullptr, nullptr, 512, 512, 0, 4, PSTR, 0, 0, 0, 0);

        add_ln_kernel<<<NT, 256>>>((i == 0) ? x : h, part, 4, PSTR,
                                   l1w + i * 512, l1b + i * 512, h, s0h, s0l);

        // ff1 = relu(...) -> bf16 splits
        gemm_bf16_kernel<<<dim3(16, 8, 1), 256, GEMM_SMEM>>>(
            s0h, s0l, wh + OFF_F1W + (size_t)i * 1048576, wl + OFF_F1W + (size_t)i * 1048576,
            f1b + i * 2048, nullptr, s1h, s1l, 2048, 512, 1, 1, 0, 0, 0, 0, 0);

        // ff2, split-K8
        gemm_bf16_kernel<<<dim3(4, 8, 8), 256, GEMM_SMEM>>>(
            s1h, s1l, wh + OFF_F2W + (size_t)i * 1048576, wl + OFF_F2W + (size_t)i * 1048576,
            f2b + i * 512, part, nullptr, nullptr, 512, 2048, 0, 8, PSTR, 0, 0, 0, 0);

        add_ln_kernel<<<NT, 256>>>(h, part, 8, PSTR,
                                   l2w + i * 512, l2b + i * 512, h, s0h, s0l);
    }

    // final encoder LN
    add_ln_kernel<<<NT, 256>>>(h, (const float*)nullptr, 0, 0, flw, flb, h, s0h, s0l);

    // ---- 4 projection MLPs, batched via blockIdx.z ----
    const int ZW = 262144, ZB = 512, ZC = NT * DD;
    gemm_bf16_kernel<<<dim3(4, 8, 4), 256, GEMM_SMEM>>>(
        s0h, s0l, wh + OFF_W0, wl + OFF_W0, b0, nullptr, s1h, s1l,
        512, 512, 1, 1, 0, 0, ZW, ZB, ZC);
    gemm_bf16_kernel<<<dim3(4, 8, 4), 256, GEMM_SMEM>>>(
        s1h, s1l, wh + OFF_W1, wl + OFF_W1, b1, nullptr, s0h, s0l,
        512, 512, 1, 1, 0, ZC, ZW, ZB, ZC);
    // mlp2: split-K2 per z -> 8 partial slabs (z-major pairs)
    gemm_bf16_kernel<<<dim3(4, 8, 8), 256, GEMM_SMEM>>>(
        s0h, s0l, wh + OFF_W2, wl + OFF_W2, b2, part, nullptr, nullptr,
        512, 512, 0, 2, PSTR, ZC, ZW, ZB, 2 * PSTR);

    // sub/obj/vsub/vobj assembly + Wv + obj split
    mul_split_kernel<<<512, 256>>>(part, subS, Wv, s1h, s1l);

    // relation tensor: (8, 128, 128, 128) on tensor cores
    final_tc_kernel<<<dim3(SS, LL), 256, REL_SMEM>>>(subS, s1h, s1l, Wv, out);
}

// round 9
// speedup vs baseline: 1.0726x; 1.0726x over previous
#include <cuda_runtime.h>
#include <cuda_bf16.h>
#include <math.h>
#include <stdint.h>

// ---------------------------------------------------------------------------
// GraphDecoder on tensor cores (mma.sync bf16, 3-term hi/lo split, fp32 acc).
// Round 9:
//  - GEMM tile 128x64 (grid x2 everywhere, 24KB/stage, 2 CTAs/SM co-resident)
//    with R8's single-sync 3-stage pipeline + term-outermost MMA
//  - relation kernel reverted to the R7 structure (measured best)
// ---------------------------------------------------------------------------

#define LL  8
#define SS  128
#define DD  512
#define HH  8
#define HDD 64
#define NT  1024

typedef __nv_bfloat16 bf16;

// ---- persistent scratch ----------------------------------------------------
#define OFF_AIW 0            // 3 x 786432
#define OFF_AOW 2359296      // 3 x 262144
#define OFF_F1W 3145728      // 3 x 1048576
#define OFF_F2W 6291456      // 3 x 1048576
#define OFF_W0  9437184      // 4 x 262144
#define OFF_W1  10485760
#define OFF_W2  11534336
#define WTOT    12582912

#define PSTR  (NT * DD)           // 524288 floats per partial slab
#define QPSTR (NT * 3 * DD)       // qkv partial stride

__device__ bf16  g_wh[WTOT], g_wl[WTOT];
__device__ bf16  g_s0h[4 * NT * DD], g_s0l[4 * NT * DD];
__device__ bf16  g_s1h[4 * NT * DD], g_s1l[4 * NT * DD];
__device__ float g_h[NT * DD];
__device__ float g_qkv[2 * NT * 3 * DD];   // 2 split-K partials
__device__ float g_part[8 * NT * DD];      // split-K partial arena
__device__ float g_Wv[NT * DD];
__device__ float g_sub[NT * DD];

// ========================= low-level helpers ================================
__device__ __forceinline__ uint32_t smem_u32(const void* p) {
    uint32_t a;
    asm("{ .reg .u64 t; cvta.to.shared.u64 t, %1; cvt.u32.u64 %0, t; }"
        : "=r"(a) : "l"(p));
    return a;
}

// swizzle for 64-byte rows: XOR bits [4:6) with bits [7:9)
__device__ __forceinline__ uint32_t swz(uint32_t off) {
    return off ^ (((off >> 7) & 3u) << 4);
}

__device__ __forceinline__ void ldmx4(uint32_t* r, uint32_t addr) {
    asm volatile("ldmatrix.sync.aligned.m8n8.x4.shared.b16 {%0,%1,%2,%3}, [%4];"
        : "=r"(r[0]), "=r"(r[1]), "=r"(r[2]), "=r"(r[3]) : "r"(addr));
}

__device__ __forceinline__ void mma16816(float* d, const uint32_t* a,
                                         const uint32_t* b) {
    asm volatile(
        "mma.sync.aligned.m16n8k16.row.col.f32.bf16.bf16.f32 "
        "{%0,%1,%2,%3}, {%4,%5,%6,%7}, {%8,%9}, {%0,%1,%2,%3};"
        : "+f"(d[0]), "+f"(d[1]), "+f"(d[2]), "+f"(d[3])
        : "r"(a[0]), "r"(a[1]), "r"(a[2]), "r"(a[3]), "r"(b[0]), "r"(b[1]));
}

__device__ __forceinline__ void cp16(uint32_t smem, const void* g) {
    asm volatile("cp.async.cg.shared.global [%0], [%1], 16;"
        :: "r"(smem), "l"(g));
}
#define CP_COMMIT asm volatile("cp.async.commit_group;" ::: "memory")
#define CP_WAIT1  asm volatile("cp.async.wait_group 1;" ::: "memory")
#define CP_WAIT2  asm volatile("cp.async.wait_group 2;" ::: "memory")

__device__ __forceinline__ void split2(float x, float y, uint32_t& hi, uint32_t& lo) {
    __nv_bfloat162 h, l;
    h.x = __float2bfloat16(x); h.y = __float2bfloat16(y);
    l.x = __float2bfloat16(x - __bfloat162float(h.x));
    l.y = __float2bfloat16(y - __bfloat162float(h.y));
    hi = *(uint32_t*)&h; lo = *(uint32_t*)&l;
}

#define TILE_B 8192    // 128x32 bf16 tile (A), 64B rows, swizzled
#define TILEB_B 4096   // 64x32 bf16 tile (B in gemm kernel)

// ---------------------------------------------------------------------------
// GEMM tile-mma (128x64): term-outermost, acc[2][4][4].
// ---------------------------------------------------------------------------
__device__ __forceinline__ void tile_mma64(
    uint32_t ahB, uint32_t alB, uint32_t bhB, uint32_t blB,
    const uint32_t* a0, const uint32_t* a1, const uint32_t (*bo)[2],
    float (&acc)[2][4][4])
{
#pragma unroll
    for (int kk = 0; kk < 2; ++kk) {
        uint32_t ah[2][4], al[2][4];
        ldmx4(ah[0], ahB + a0[kk]);
        ldmx4(ah[1], ahB + a1[kk]);
        ldmx4(al[0], alB + a0[kk]);
        ldmx4(al[1], alB + a1[kk]);
        uint32_t bh[4][2], bl[4][2];
#pragma unroll
        for (int ng = 0; ng < 2; ++ng) {
            uint32_t r[4];
            ldmx4(r, bhB + bo[ng][kk]);
            bh[2*ng][0] = r[0]; bh[2*ng][1] = r[1];
            bh[2*ng+1][0] = r[2]; bh[2*ng+1][1] = r[3];
            ldmx4(r, blB + bo[ng][kk]);
            bl[2*ng][0] = r[0]; bl[2*ng][1] = r[1];
            bl[2*ng+1][0] = r[2]; bl[2*ng+1][1] = r[3];
        }
#pragma unroll
        for (int mt = 0; mt < 2; ++mt)
#pragma unroll
            for (int nt = 0; nt < 4; ++nt)
                mma16816(acc[mt][nt], ah[mt], bh[nt]);
#pragma unroll
        for (int mt = 0; mt < 2; ++mt)
#pragma unroll
            for (int nt = 0; nt < 4; ++nt)
                mma16816(acc[mt][nt], ah[mt], bl[nt]);
#pragma unroll
        for (int mt = 0; mt < 2; ++mt)
#pragma unroll
            for (int nt = 0; nt < 4; ++nt)
                mma16816(acc[mt][nt], al[mt], bh[nt]);
    }
}

// ---------------------------------------------------------------------------
// Relation tile-mma (128x128): R7 interleaved form, acc[2][8][4].
// ---------------------------------------------------------------------------
__device__ __forceinline__ void tile_mma128(
    uint32_t ahB, uint32_t alB, uint32_t bhB, uint32_t blB,
    const uint32_t* a0, const uint32_t* a1, const uint32_t (*bo)[2],
    float (&acc)[2][8][4])
{
#pragma unroll
    for (int kk = 0; kk < 2; ++kk) {
        uint32_t ah[2][4], al[2][4];
        ldmx4(ah[0], ahB + a0[kk]);
        ldmx4(al[0], alB + a0[kk]);
        ldmx4(ah[1], ahB + a1[kk]);
        ldmx4(al[1], alB + a1[kk]);
#pragma unroll
        for (int hf = 0; hf < 2; ++hf) {
            uint32_t bh[4][2], bl[4][2];
#pragma unroll
            for (int ng = 0; ng < 2; ++ng) {
                uint32_t r[4];
                ldmx4(r, bhB + bo[2 * hf + ng][kk]);
                bh[2*ng][0] = r[0]; bh[2*ng][1] = r[1];
                bh[2*ng+1][0] = r[2]; bh[2*ng+1][1] = r[3];
                ldmx4(r, blB + bo[2 * hf + ng][kk]);
                bl[2*ng][0] = r[0]; bl[2*ng][1] = r[1];
                bl[2*ng+1][0] = r[2]; bl[2*ng+1][1] = r[3];
            }
#pragma unroll
            for (int mt = 0; mt < 2; ++mt)
#pragma unroll
                for (int nt = 0; nt < 4; ++nt) {
                    mma16816(acc[mt][4*hf + nt], ah[mt], bh[nt]);
                    mma16816(acc[mt][4*hf + nt], ah[mt], bl[nt]);
                    mma16816(acc[mt][4*hf + nt], al[mt], bh[nt]);
                }
        }
    }
}

// ---------------------------------------------------------------------------
// bf16 GEMM, batched (z) + split-K (ks). C[z] = act(A[z] @ Wt[z]^T + bias[z]).
// 128x64 tile, BK=32, 3-stage ring, ONE sync/chunk, 2 CTAs/SM.
// Stage layout: Ah(8K) Al(8K) Bh(4K) Bl(4K) = 24KB.
// ---------------------------------------------------------------------------
#define G_AH 0
#define G_AL 8192
#define G_BH 16384
#define G_BL 20480
#define STAGE_BYTES 24576
#define GEMM_SMEM   (3 * STAGE_BYTES + 128)   // 73856

__global__ void __launch_bounds__(256, 2) gemm_bf16_kernel(
    const bf16* __restrict__ Ah, const bf16* __restrict__ Al,
    const bf16* __restrict__ Wh, const bf16* __restrict__ Wl,
    const float* __restrict__ bias,
    float* __restrict__ Cf, bf16* __restrict__ Ch, bf16* __restrict__ Cl,
    int N, int K, int relu, int ks, int pstr,
    int zsA, int zsW, int zsB, int zsC)
{
    extern __shared__ char smch[];
    const uint32_t base = (smem_u32(smch) + 127) & ~127u;

    const int z  = blockIdx.z / ks;
    const int kz = blockIdx.z % ks;
    const int Klocal = K / ks;
    const int kbase = kz * Klocal;

    Ah += (size_t)z * zsA;  Al += (size_t)z * zsA;
    Wh += (size_t)z * zsW;  Wl += (size_t)z * zsW;
    bias += (size_t)z * zsB;
    if (Cf) Cf += (size_t)z * zsC + (size_t)kz * pstr;
    if (Ch) { Ch += (size_t)z * zsC; Cl += (size_t)z * zsC; }

    const int tid  = threadIdx.x;
    const int lane = tid & 31;
    const int wid  = tid >> 5;
    const int wm   = wid & 3;           // m: 4 x 32
    const int wn   = wid >> 2;          // n: 2 x 32
    const int m0 = blockIdx.y * 128;
    const int n0 = blockIdx.x * 64;

    // per-thread cp.async descriptors: 6 x 16B chunks per stage (1536 total)
    const bf16* gsrc[6];
    uint32_t sdst[6];
#pragma unroll
    for (int it = 0; it < 6; ++it) {
        int c = tid + it * 256;
        int q = c & 3;
        const bf16* p;
        uint32_t off;
        if (c < 1024) {                       // A tiles: 128 rows
            int row = (c & 511) >> 2;
            p = (c < 512 ? Ah : Al) + (size_t)(m0 + row) * K;
            off = (c < 512 ? G_AH : G_AL) + swz(row * 64 + q * 16);
        } else {                              // B tiles: 64 rows
            int row = (c & 255) >> 2;
            p = (c < 1280 ? Wh : Wl) + (size_t)(n0 + row) * K;
            off = (c < 1280 ? G_BH : G_BL) + swz(row * 64 + q * 16);
        }
        gsrc[it] = p + kbase + q * 8;
        sdst[it] = off;
    }

    const int nch = Klocal >> 5;
    auto issue = [&](int s) {
        uint32_t st = base + (s % 3) * STAGE_BYTES;
#pragma unroll
        for (int it = 0; it < 6; ++it)
            cp16(st + sdst[it], gsrc[it] + s * 32);
    };
    issue(0); CP_COMMIT;
    issue(1); CP_COMMIT;

    const int aRow = wm * 32 + (lane & 15);
    const int aCol = (lane >> 4) * 8;
    const int bRow = wn * 32 + (lane & 7) + ((lane >> 4) << 3);
    const int bCol = ((lane >> 3) & 1) * 8;
    uint32_t a0[2], a1[2], bo[2][2];
#pragma unroll
    for (int kk = 0; kk < 2; ++kk) {
        a0[kk] = swz(aRow * 64 + aCol * 2 + kk * 32);
        a1[kk] = swz((aRow + 16) * 64 + aCol * 2 + kk * 32);
#pragma unroll
        for (int ng = 0; ng < 2; ++ng)
            bo[ng][kk] = swz((bRow + ng * 16) * 64 + bCol * 2 + kk * 32);
    }

    float acc[2][4][4] = {};

    for (int s = 0; s < nch; ++s) {
        CP_WAIT1;                 // stage s arrived
        __syncthreads();          // all warps done with stage s-1
        if (s + 2 < nch) issue(s + 2);   // -> buffer (s-1)%3, drained
        CP_COMMIT;
        uint32_t st = base + (s % 3) * STAGE_BYTES;
        tile_mma64(st + G_AH, st + G_AL, st + G_BH, st + G_BL,
                   a0, a1, bo, acc);
    }

    const int addb = (kz == 0);
#pragma unroll
    for (int mt = 0; mt < 2; ++mt) {
        int r0 = m0 + wm * 32 + mt * 16 + (lane >> 2);
#pragma unroll
        for (int nt = 0; nt < 4; ++nt) {
            int col = n0 + wn * 32 + nt * 8 + (lane & 3) * 2;
            float b0 = addb ? bias[col] : 0.f, b1 = addb ? bias[col + 1] : 0.f;
            float v0 = acc[mt][nt][0] + b0, v1 = acc[mt][nt][1] + b1;
            float v2 = acc[mt][nt][2] + b0, v3 = acc[mt][nt][3] + b1;
            if (relu) {
                v0 = fmaxf(v0, 0.f); v1 = fmaxf(v1, 0.f);
                v2 = fmaxf(v2, 0.f); v3 = fmaxf(v3, 0.f);
            }
            if (Ch) {
                uint32_t hh, ll;
                split2(v0, v1, hh, ll);
                *(uint32_t*)&Ch[(size_t)r0 * N + col] = hh;
                *(uint32_t*)&Cl[(size_t)r0 * N + col] = ll;
                split2(v2, v3, hh, ll);
                *(uint32_t*)&Ch[(size_t)(r0 + 8) * N + col] = hh;
                *(uint32_t*)&Cl[(size_t)(r0 + 8) * N + col] = ll;
            } else {
                *(float2*)&Cf[(size_t)r0 * N + col]       = make_float2(v0, v1);
                *(float2*)&Cf[(size_t)(r0 + 8) * N + col] = make_float2(v2, v3);
            }
        }
    }
}

// ---------------------------------------------------------------------------
// Relation tensor (R7 structure): per block (b,i):
//   out[b,i,:,:] = ((sub_b * W_bi) @ obj_b^T)
// A: fp32 load+scale+split, 2-buffer; B: 3-stage cp.async; two syncs/chunk.
// ---------------------------------------------------------------------------
#define RA_STAGE (2 * TILE_B)   // Ah, Al
#define RB_STAGE (2 * TILE_B)   // Bh, Bl
#define REL_SMEM (2048 + 2 * RA_STAGE + 3 * RB_STAGE + 128)  // 84096

__global__ void __launch_bounds__(256, 2) final_tc_kernel(
    const float* __restrict__ sub, const bf16* __restrict__ objh,
    const bf16* __restrict__ objl, const float* __restrict__ Wv,
    float* __restrict__ out)
{
    extern __shared__ char smch[];
    const uint32_t sb = (smem_u32(smch) + 127) & ~127u;
    float* ws = (float*)(smch + (sb - smem_u32(smch)));
    char* aPtr = (char*)ws + 2048;
    const uint32_t aBase = sb + 2048;
    const uint32_t bBase = aBase + 2 * RA_STAGE;

    const int i = blockIdx.x;
    const int b = blockIdx.y;
    const int tid  = threadIdx.x;
    const int lane = tid & 31;
    const int wid  = tid >> 5;
    const int wm   = wid & 3;
    const int wn   = wid >> 2;

    const float* wrow = Wv + (size_t)(b * SS + i) * DD;
    ws[tid]       = wrow[tid];
    ws[tid + 256] = wrow[tid + 256];

    const float* subB = sub + (size_t)b * SS * DD;
    const bf16* ohB = objh + (size_t)b * SS * DD;
    const bf16* olB = objl + (size_t)b * SS * DD;

    const bf16* bsrc[4];
    uint32_t bdst[4];
#pragma unroll
    for (int it = 0; it < 4; ++it) {
        int c = tid + it * 256;
        int a = c >> 9, idx = c & 511, row = idx >> 2, q = idx & 3;
        bsrc[it] = (a ? olB : ohB) + (size_t)row * DD + q * 8;
        bdst[it] = a * TILE_B + swz(row * 64 + q * 16);
    }
    int aLrow[4], aLc4[4];
#pragma unroll
    for (int it = 0; it < 4; ++it) {
        int idx = tid + it * 256;
        aLrow[it] = idx >> 3;
        aLc4[it]  = (idx & 7) << 2;
    }

    auto issueB = [&](int s) {
        uint32_t st = bBase + (s % 3) * RB_STAGE;
#pragma unroll
        for (int it = 0; it < 4; ++it)
            cp16(st + bdst[it], bsrc[it] + s * 32);
    };
    auto loadA = [&](int s, float4* r) {
#pragma unroll
        for (int it = 0; it < 4; ++it)
            r[it] = *(const float4*)&subB[(size_t)aLrow[it] * DD + s * 32 + aLc4[it]];
    };
    auto storeA = [&](int s, const float4* r) {
        char* dh = aPtr + (s & 1) * RA_STAGE;
        int kc = s * 32;
#pragma unroll
        for (int it = 0; it < 4; ++it) {
            float4 v = r[it];
            v.x *= ws[kc + aLc4[it]];     v.y *= ws[kc + aLc4[it] + 1];
            v.z *= ws[kc + aLc4[it] + 2]; v.w *= ws[kc + aLc4[it] + 3];
            uint32_t h0, h1, l0, l1;
            split2(v.x, v.y, h0, l0);
            split2(v.z, v.w, h1, l1);
            uint32_t off = swz(aLrow[it] * 64 + aLc4[it] * 2);
            *(uint2*)(dh + off)          = make_uint2(h0, h1);
            *(uint2*)(dh + TILE_B + off) = make_uint2(l0, l1);
        }
    };

    issueB(0); CP_COMMIT;
    issueB(1); CP_COMMIT;
    issueB(2); CP_COMMIT;
    __syncthreads();              // ws visible
    {
        float4 r0[4];
        loadA(0, r0);
        storeA(0, r0);
    }

    const int aRow = wm * 32 + (lane & 15);
    const int aCol = (lane >> 4) * 8;
    const int bRow = wn * 64 + (lane & 7) + ((lane >> 4) << 3);
    const int bCol = ((lane >> 3) & 1) * 8;
    uint32_t a0[2], a1[2], bo[4][2];
#pragma unroll
    for (int kk = 0; kk < 2; ++kk) {
        a0[kk] = swz(aRow * 64 + aCol * 2 + kk * 32);
        a1[kk] = swz((aRow + 16) * 64 + aCol * 2 + kk * 32);
#pragma unroll
        for (int ng = 0; ng < 4; ++ng)
            bo[ng][kk] = swz((bRow + ng * 16) * 64 + bCol * 2 + kk * 32);
    }

    float acc[2][8][4] = {};
    float4 pre[4];

    for (int s = 0; s < 16; ++s) {
        if (s + 1 < 16) loadA(s + 1, pre);
        CP_WAIT2;
        __syncthreads();
        uint32_t aB = aBase + (s & 1) * RA_STAGE;
        uint32_t bB = bBase + (s % 3) * RB_STAGE;
        tile_mma128(aB, aB + TILE_B, bB, bB + TILE_B, a0, a1, bo, acc);
        __syncthreads();
        if (s + 1 < 16) storeA(s + 1, pre);
        if (s + 3 < 16) issueB(s + 3);
        CP_COMMIT;
    }

    float* outB = out + (size_t)(b * SS + i) * SS * SS;
#pragma unroll
    for (int mt = 0; mt < 2; ++mt) {
        int r0 = wm * 32 + mt * 16 + (lane >> 2);
#pragma unroll
        for (int nt = 0; nt < 8; ++nt) {
            int col = wn * 64 + nt * 8 + (lane & 3) * 2;
            *(float2*)&outB[(size_t)r0 * SS + col] =
                make_float2(acc[mt][nt][0], acc[mt][nt][1]);
            *(float2*)&outB[(size_t)(r0 + 8) * SS + col] =
                make_float2(acc[mt][nt][2], acc[mt][nt][3]);
        }
    }
}

// ---------------------------------------------------------------------------
// Attention over axis L per (s, h); sums 2 qkv split-K partials; bf16 hi/lo out.
// ---------------------------------------------------------------------------
__global__ void attn_kernel(const float* __restrict__ qkv,
                            bf16* __restrict__ oh, bf16* __restrict__ ol)
{
    const int s = blockIdx.x;
    const int h = blockIdx.y;
    const int t = threadIdx.x;  // 0..63

    __shared__ float qs[8][65], ks[8][65], vs[8][65];
    __shared__ float at[8][9];

#pragma unroll
    for (int l = 0; l < 8; ++l) {
        size_t base = (size_t)(l * SS + s) * (3 * DD) + h * HDD + t;
        qs[l][t] = qkv[base]          + qkv[base + QPSTR];
        ks[l][t] = qkv[base + DD]     + qkv[base + DD + QPSTR];
        vs[l][t] = qkv[base + 2 * DD] + qkv[base + 2 * DD + QPSTR];
    }
    __syncthreads();

    const int l = t >> 3;
    const int m = t & 7;
    float sc = 0.0f;
#pragma unroll
    for (int d = 0; d < HDD; ++d) sc += qs[l][d] * ks[m][d];
    sc *= 0.125f;

    float mx = sc;
#pragma unroll
    for (int off = 1; off < 8; off <<= 1)
        mx = fmaxf(mx, __shfl_xor_sync(0xffffffffu, mx, off));
    float e = __expf(sc - mx);
    float sm = e;
#pragma unroll
    for (int off = 1; off < 8; off <<= 1)
        sm += __shfl_xor_sync(0xffffffffu, sm, off);
    at[l][m] = e / sm;
    __syncthreads();

    const int dg = (t & 7) * 8;
    float accv[8] = {};
#pragma unroll
    for (int mm = 0; mm < 8; ++mm) {
        float a = at[l][mm];
#pragma unroll
        for (int j = 0; j < 8; ++j)
            accv[j] = fmaf(a, vs[mm][dg + j], accv[j]);
    }
    size_t ob = (size_t)(l * SS + s) * DD + h * HDD + dg;
#pragma unroll
    for (int j = 0; j < 8; j += 2) {
        uint32_t hh, ll;
        split2(accv[j], accv[j + 1], hh, ll);
        *(uint32_t*)&oh[ob + j] = hh;
        *(uint32_t*)&ol[ob + j] = ll;
    }
}

// ---------------------------------------------------------------------------
// out = LayerNorm(a + sum_{p<np} P[p*pstr + .]); emits bf16 hi/lo if outh.
// ---------------------------------------------------------------------------
__global__ void add_ln_kernel(const float* __restrict__ a,
                              const float* __restrict__ P, int np, int pstr,
                              const float* __restrict__ gam, const float* __restrict__ bet,
                              float* __restrict__ out,
                              bf16* __restrict__ outh, bf16* __restrict__ outl)
{
    const int row = blockIdx.x;
    const int t = threadIdx.x;
    const size_t base = (size_t)row * DD;
    const int c = 2 * t;

    float v0 = a[base + c];
    float v1 = a[base + c + 1];
    for (int p = 0; p < np; ++p) {
        v0 += P[(size_t)p * pstr + base + c];
        v1 += P[(size_t)p * pstr + base + c + 1];
    }

    float s = v0 + v1;
    float q = v0 * v0 + v1 * v1;

    __shared__ float sred[16];
#pragma unroll
    for (int off = 16; off > 0; off >>= 1) {
        s += __shfl_xor_sync(0xffffffffu, s, off);
        q += __shfl_xor_sync(0xffffffffu, q, off);
    }
    if ((t & 31) == 0) { sred[t >> 5] = s; sred[(t >> 5) + 8] = q; }
    __syncthreads();
    if (t < 32) {
        float ss = (t < 8) ? sred[t] : 0.0f;
        float qq = (t < 8) ? sred[t + 8] : 0.0f;
#pragma unroll
        for (int off = 4; off > 0; off >>= 1) {
            ss += __shfl_xor_sync(0xffffffffu, ss, off);
            qq += __shfl_xor_sync(0xffffffffu, qq, off);
        }
        if (t == 0) { sred[0] = ss; sred[1] = qq; }
    }
    __syncthreads();

    const float mean = sred[0] * (1.0f / 512.0f);
    const float var  = sred[1] * (1.0f / 512.0f) - mean * mean;
    const float rstd = rsqrtf(var + 1e-5f);

    float y0 = (v0 - mean) * rstd * gam[c]     + bet[c];
    float y1 = (v1 - mean) * rstd * gam[c + 1] + bet[c + 1];
    *(float2*)&out[base + c] = make_float2(y0, y1);
    if (outh) {
        uint32_t hh, ll;
        split2(y0, y1, hh, ll);
        *(uint32_t*)&outh[base + c] = hh;
        *(uint32_t*)&outl[base + c] = ll;
    }
}

// ---------------------------------------------------------------------------
// Fused splitter: 8 segments of fp32 -> bf16 hi/lo (one launch).
// ---------------------------------------------------------------------------
struct SplitArgs {
    const float* src[8];
    bf16* dh[8];
    bf16* dl[8];
    int bstart[9];
};

__global__ void fused_split_kernel(SplitArgs sa)
{
    int blk = blockIdx.x;
    int seg = 0;
#pragma unroll
    for (int s = 1; s < 8; ++s) seg += (blk >= sa.bstart[s]);
    int idx = (blk - sa.bstart[seg]) * 256 + threadIdx.x;
    float4 x = ((const float4*)sa.src[seg])[idx];
    uint32_t h0, h1, l0, l1;
    split2(x.x, x.y, h0, l0);
    split2(x.z, x.w, h1, l1);
    ((uint2*)sa.dh[seg])[idx] = make_uint2(h0, h1);
    ((uint2*)sa.dl[seg])[idx] = make_uint2(l0, l1);
}

// ---------------------------------------------------------------------------
// Consumes 8 mlp2 split-K2 partial slabs (z-major pairs):
//   sub = P0+P1; obj = P2+P3 -> bf16 hi/lo; Wv = (P4+P5)*(P6+P7).
// ---------------------------------------------------------------------------
__global__ void mul_split_kernel(const float* __restrict__ P,
                                 float* __restrict__ subS, float* __restrict__ Wv,
                                 bf16* __restrict__ oh, bf16* __restrict__ ol)
{
    int i = blockIdx.x * blockDim.x + threadIdx.x;   // float4 index
    const float4* P4 = (const float4*)P;
    const int S4 = PSTR / 4;

    float4 s0 = P4[i], s1 = P4[i + S4];
    ((float4*)subS)[i] = make_float4(s0.x + s1.x, s0.y + s1.y,
                                     s0.z + s1.z, s0.w + s1.w);

    float4 o0 = P4[i + 2 * S4], o1 = P4[i + 3 * S4];
    float ox = o0.x + o1.x, oy = o0.y + o1.y, oz = o0.z + o1.z, ow = o0.w + o1.w;
    uint32_t h0, h1, l0, l1;
    split2(ox, oy, h0, l0);
    split2(oz, ow, h1, l1);
    ((uint2*)oh)[i] = make_uint2(h0, h1);
    ((uint2*)ol)[i] = make_uint2(l0, l1);

    float4 a0 = P4[i + 4 * S4], a1 = P4[i + 5 * S4];
    float4 b0 = P4[i + 6 * S4], b1 = P4[i + 7 * S4];
    ((float4*)Wv)[i] = make_float4((a0.x + a1.x) * (b0.x + b1.x),
                                   (a0.y + a1.y) * (b0.y + b1.y),
                                   (a0.z + a1.z) * (b0.z + b1.z),
                                   (a0.w + a1.w) * (b0.w + b1.w));
}

// ---------------------------------------------------------------------------
extern "C" void kernel_launch(void* const* d_in, const int* in_sizes, int n_in,
                              void* d_out, int out_size)
{
    const float* x   = (const float*)d_in[0];
    const float* aiw = (const float*)d_in[1];
    const float* aib = (const float*)d_in[2];
    const float* aow = (const float*)d_in[3];
    const float* aob = (const float*)d_in[4];
    const float* l1w = (const float*)d_in[5];
    const float* l1b = (const float*)d_in[6];
    const float* l2w = (const float*)d_in[7];
    const float* l2b = (const float*)d_in[8];
    const float* f1w = (const float*)d_in[9];
    const float* f1b = (const float*)d_in[10];
    const float* f2w = (const float*)d_in[11];
    const float* f2b = (const float*)d_in[12];
    const float* flw = (const float*)d_in[13];
    const float* flb = (const float*)d_in[14];
    const float* w0  = (const float*)d_in[15];
    const float* b0  = (const float*)d_in[16];
    const float* w1  = (const float*)d_in[17];
    const float* b1  = (const float*)d_in[18];
    const float* w2  = (const float*)d_in[19];
    const float* b2  = (const float*)d_in[20];
    float* out = (float*)d_out;

    bf16 *wh, *wl, *s0h, *s0l, *s1h, *s1l;
    float *h, *qkv, *part, *Wv, *subS;
    cudaGetSymbolAddress((void**)&wh,   g_wh);
    cudaGetSymbolAddress((void**)&wl,   g_wl);
    cudaGetSymbolAddress((void**)&s0h,  g_s0h);
    cudaGetSymbolAddress((void**)&s0l,  g_s0l);
    cudaGetSymbolAddress((void**)&s1h,  g_s1h);
    cudaGetSymbolAddress((void**)&s1l,  g_s1l);
    cudaGetSymbolAddress((void**)&h,    g_h);
    cudaGetSymbolAddress((void**)&qkv,  g_qkv);
    cudaGetSymbolAddress((void**)&part, g_part);
    cudaGetSymbolAddress((void**)&Wv,   g_Wv);
    cudaGetSymbolAddress((void**)&subS, g_sub);

    cudaFuncSetAttribute(gemm_bf16_kernel,
                         cudaFuncAttributeMaxDynamicSharedMemorySize, GEMM_SMEM);
    cudaFuncSetAttribute(final_tc_kernel,
                         cudaFuncAttributeMaxDynamicSharedMemorySize, REL_SMEM);

    // ---- launch 1: all splits fused (weights + x) ----
    {
        SplitArgs sa;
        sa.src[0] = aiw; sa.dh[0] = wh + OFF_AIW; sa.dl[0] = wl + OFF_AIW;
        sa.src[1] = aow; sa.dh[1] = wh + OFF_AOW; sa.dl[1] = wl + OFF_AOW;
        sa.src[2] = f1w; sa.dh[2] = wh + OFF_F1W; sa.dl[2] = wl + OFF_F1W;
        sa.src[3] = f2w; sa.dh[3] = wh + OFF_F2W; sa.dl[3] = wl + OFF_F2W;
        sa.src[4] = w0;  sa.dh[4] = wh + OFF_W0;  sa.dl[4] = wl + OFF_W0;
        sa.src[5] = w1;  sa.dh[5] = wh + OFF_W1;  sa.dl[5] = wl + OFF_W1;
        sa.src[6] = w2;  sa.dh[6] = wh + OFF_W2;  sa.dl[6] = wl + OFF_W2;
        sa.src[7] = x;   sa.dh[7] = s0h;          sa.dl[7] = s0l;
        int sizes[8] = {2359296, 786432, 3145728, 3145728,
                        1048576, 1048576, 1048576, 524288};
        int acc = 0;
        for (int s = 0; s < 8; ++s) { sa.bstart[s] = acc; acc += sizes[s] / 1024; }
        sa.bstart[8] = acc;
        fused_split_kernel<<<acc, 256>>>(sa);
    }

    // ---- encoder: 3 post-norm layers ----
    for (int i = 0; i < 3; ++i) {
        // qkv, split-K2 -> 2 partials in g_qkv : grid (24,8,2)=384
        gemm_bf16_kernel<<<dim3(24, 8, 2), 256, GEMM_SMEM>>>(
            s0h, s0l, wh + OFF_AIW + (size_t)i * 786432, wl + OFF_AIW + (size_t)i * 786432,
            aib + i * 1536, qkv, nullptr, nullptr, 1536, 512, 0, 2, QPSTR, 0, 0, 0, 0);

        attn_kernel<<<dim3(SS, HH), 64>>>(qkv, s1h, s1l);

        // attn-out, split-K4 (launch 4 on i=0: ncu slot): grid (8,8,4)=256
        gemm_bf16_kernel<<<dim3(8, 8, 4), 256, GEMM_SMEM>>>(
            s1h, s1l, wh + OFF_AOW + (size_t)i * 262144, wl + OFF_AOW + (size_t)i * 262144,
            aob + i * 512, part, nullptr, nullptr, 512, 512, 0, 4, PSTR, 0, 0, 0, 0);

        add_ln_kernel<<<NT, 256>>>((i == 0) ? x : h, part, 4, PSTR,
                                   l1w + i * 512, l1b + i * 512, h, s0h, s0l);

        // ff1 = relu(...) -> bf16 splits : grid (32,8)=256
        gemm_bf16_kernel<<<dim3(32, 8, 1), 256, GEMM_SMEM>>>(
            s0h, s0l, wh + OFF_F1W + (size_t)i * 1048576, wl + OFF_F1W + (size_t)i * 1048576,
            f1b + i * 2048, nullptr, s1h, s1l, 2048, 512, 1, 1, 0, 0, 0, 0, 0);

        // ff2, split-K8 : grid (8,8,8)=512
        gemm_bf16_kernel<<<dim3(8, 8, 8), 256, GEMM_SMEM>>>(
            s1h, s1l, wh + OFF_F2W + (size_t)i * 1048576, wl + OFF_F2W + (size_t)i * 1048576,
            f2b + i * 512, part, nullptr, nullptr, 512, 2048, 0, 8, PSTR, 0, 0, 0, 0);

        add_ln_kernel<<<NT, 256>>>(h, part, 8, PSTR,
                                   l2w + i * 512, l2b + i * 512, h, s0h, s0l);
    }

    // final encoder LN
    add_ln_kernel<<<NT, 256>>>(h, (const float*)nullptr, 0, 0, flw, flb, h, s0h, s0l);

    // ---- 4 projection MLPs, batched via blockIdx.z ----
    const int ZW = 262144, ZB = 512, ZC = NT * DD;
    gemm_bf16_kernel<<<dim3(8, 8, 4), 256, GEMM_SMEM>>>(
        s0h, s0l, wh + OFF_W0, wl + OFF_W0, b0, nullptr, s1h, s1l,
        512, 512, 1, 1, 0, 0, ZW, ZB, ZC);
    gemm_bf16_kernel<<<dim3(8, 8, 4), 256, GEMM_SMEM>>>(
        s1h, s1l, wh + OFF_W1, wl + OFF_W1, b1, nullptr, s0h, s0l,
        512, 512, 1, 1, 0, ZC, ZW, ZB, ZC);
    // mlp2: split-K2 per z -> 8 partial slabs (z-major pairs): grid (8,8,8)=512
    gemm_bf16_kernel<<<dim3(8, 8, 8), 256, GEMM_SMEM>>>(
        s0h, s0l, wh + OFF_W2, wl + OFF_W2, b2, part, nullptr, nullptr,
        512, 512, 0, 2, PSTR, ZC, ZW, ZB, 2 * PSTR);

    // sub/obj/vsub/vobj assembly + Wv + obj split
    mul_split_kernel<<<512, 256>>>(part, subS, Wv, s1h, s1l);

    // relation tensor: (8, 128, 128, 128) on tensor cores
    final_tc_kernel<<<dim3(SS, LL), 256, REL_SMEM>>>(subS, s1h, s1l, Wv, out);
}

// round 10
// speedup vs baseline: 1.0890x; 1.0153x over previous
#include <cuda_runtime.h>
#include <cuda_bf16.h>
#include <math.h>
#include <stdint.h>

// ---------------------------------------------------------------------------
// GraphDecoder on tensor cores (mma.sync bf16, 3-term hi/lo split, fp32 acc).
// Round 10 (GEMM kernel only; relation kernel = R9 best):
//  - 4-stage cp.async ring (96KB, 2 CTAs/SM) -> 3 chunk-times of lookahead
//  - A-fragment prefetch across kk inside tile_mma64
// ---------------------------------------------------------------------------

#define LL  8
#define SS  128
#define DD  512
#define HH  8
#define HDD 64
#define NT  1024

typedef __nv_bfloat16 bf16;

// ---- persistent scratch ----------------------------------------------------
#define OFF_AIW 0            // 3 x 786432
#define OFF_AOW 2359296      // 3 x 262144
#define OFF_F1W 3145728      // 3 x 1048576
#define OFF_F2W 6291456      // 3 x 1048576
#define OFF_W0  9437184      // 4 x 262144
#define OFF_W1  10485760
#define OFF_W2  11534336
#define WTOT    12582912

#define PSTR  (NT * DD)           // 524288 floats per partial slab
#define QPSTR (NT * 3 * DD)       // qkv partial stride

__device__ bf16  g_wh[WTOT], g_wl[WTOT];
__device__ bf16  g_s0h[4 * NT * DD], g_s0l[4 * NT * DD];
__device__ bf16  g_s1h[4 * NT * DD], g_s1l[4 * NT * DD];
__device__ float g_h[NT * DD];
__device__ float g_qkv[2 * NT * 3 * DD];   // 2 split-K partials
__device__ float g_part[8 * NT * DD];      // split-K partial arena
__device__ float g_Wv[NT * DD];
__device__ float g_sub[NT * DD];

// ========================= low-level helpers ================================
__device__ __forceinline__ uint32_t smem_u32(const void* p) {
    uint32_t a;
    asm("{ .reg .u64 t; cvta.to.shared.u64 t, %1; cvt.u32.u64 %0, t; }"
        : "=r"(a) : "l"(p));
    return a;
}

// swizzle for 64-byte rows: XOR bits [4:6) with bits [7:9)
__device__ __forceinline__ uint32_t swz(uint32_t off) {
    return off ^ (((off >> 7) & 3u) << 4);
}

__device__ __forceinline__ void ldmx4(uint32_t* r, uint32_t addr) {
    asm volatile("ldmatrix.sync.aligned.m8n8.x4.shared.b16 {%0,%1,%2,%3}, [%4];"
        : "=r"(r[0]), "=r"(r[1]), "=r"(r[2]), "=r"(r[3]) : "r"(addr));
}

__device__ __forceinline__ void mma16816(float* d, const uint32_t* a,
                                         const uint32_t* b) {
    asm volatile(
        "mma.sync.aligned.m16n8k16.row.col.f32.bf16.bf16.f32 "
        "{%0,%1,%2,%3}, {%4,%5,%6,%7}, {%8,%9}, {%0,%1,%2,%3};"
        : "+f"(d[0]), "+f"(d[1]), "+f"(d[2]), "+f"(d[3])
        : "r"(a[0]), "r"(a[1]), "r"(a[2]), "r"(a[3]), "r"(b[0]), "r"(b[1]));
}

__device__ __forceinline__ void cp16(uint32_t smem, const void* g) {
    asm volatile("cp.async.cg.shared.global [%0], [%1], 16;"
        :: "r"(smem), "l"(g));
}
#define CP_COMMIT asm volatile("cp.async.commit_group;" ::: "memory")
#define CP_WAIT2  asm volatile("cp.async.wait_group 2;" ::: "memory")

__device__ __forceinline__ void split2(float x, float y, uint32_t& hi, uint32_t& lo) {
    __nv_bfloat162 h, l;
    h.x = __float2bfloat16(x); h.y = __float2bfloat16(y);
    l.x = __float2bfloat16(x - __bfloat162float(h.x));
    l.y = __float2bfloat16(y - __bfloat162float(h.y));
    hi = *(uint32_t*)&h; lo = *(uint32_t*)&l;
}

#define TILE_B 8192    // 128x32 bf16 tile (A), 64B rows, swizzled

// ---------------------------------------------------------------------------
// GEMM tile-mma (128x64): A fragments for BOTH kk prefetched up front,
// then per-kk B loads + term-outermost MMAs. acc[2][4][4].
// ---------------------------------------------------------------------------
__device__ __forceinline__ void tile_mma64(
    uint32_t ahB, uint32_t alB, uint32_t bhB, uint32_t blB,
    const uint32_t* a0, const uint32_t* a1, const uint32_t (*bo)[2],
    float (&acc)[2][4][4])
{
    uint32_t ah[2][2][4], al[2][2][4];   // [kk][mt][4]
#pragma unroll
    for (int kk = 0; kk < 2; ++kk) {
        ldmx4(ah[kk][0], ahB + a0[kk]);
        ldmx4(ah[kk][1], ahB + a1[kk]);
        ldmx4(al[kk][0], alB + a0[kk]);
        ldmx4(al[kk][1], alB + a1[kk]);
    }
#pragma unroll
    for (int kk = 0; kk < 2; ++kk) {
        uint32_t bh[4][2], bl[4][2];
#pragma unroll
        for (int ng = 0; ng < 2; ++ng) {
            uint32_t r[4];
            ldmx4(r, bhB + bo[ng][kk]);
            bh[2*ng][0] = r[0]; bh[2*ng][1] = r[1];
            bh[2*ng+1][0] = r[2]; bh[2*ng+1][1] = r[3];
            ldmx4(r, blB + bo[ng][kk]);
            bl[2*ng][0] = r[0]; bl[2*ng][1] = r[1];
            bl[2*ng+1][0] = r[2]; bl[2*ng+1][1] = r[3];
        }
#pragma unroll
        for (int mt = 0; mt < 2; ++mt)
#pragma unroll
            for (int nt = 0; nt < 4; ++nt)
                mma16816(acc[mt][nt], ah[kk][mt], bh[nt]);
#pragma unroll
        for (int mt = 0; mt < 2; ++mt)
#pragma unroll
            for (int nt = 0; nt < 4; ++nt)
                mma16816(acc[mt][nt], ah[kk][mt], bl[nt]);
#pragma unroll
        for (int mt = 0; mt < 2; ++mt)
#pragma unroll
            for (int nt = 0; nt < 4; ++nt)
                mma16816(acc[mt][nt], al[kk][mt], bh[nt]);
    }
}

// ---------------------------------------------------------------------------
// Relation tile-mma (128x128): R7/R9 interleaved form, acc[2][8][4].
// ---------------------------------------------------------------------------
__device__ __forceinline__ void tile_mma128(
    uint32_t ahB, uint32_t alB, uint32_t bhB, uint32_t blB,
    const uint32_t* a0, const uint32_t* a1, const uint32_t (*bo)[2],
    float (&acc)[2][8][4])
{
#pragma unroll
    for (int kk = 0; kk < 2; ++kk) {
        uint32_t ah[2][4], al[2][4];
        ldmx4(ah[0], ahB + a0[kk]);
        ldmx4(al[0], alB + a0[kk]);
        ldmx4(ah[1], ahB + a1[kk]);
        ldmx4(al[1], alB + a1[kk]);
#pragma unroll
        for (int hf = 0; hf < 2; ++hf) {
            uint32_t bh[4][2], bl[4][2];
#pragma unroll
            for (int ng = 0; ng < 2; ++ng) {
                uint32_t r[4];
                ldmx4(r, bhB + bo[2 * hf + ng][kk]);
                bh[2*ng][0] = r[0]; bh[2*ng][1] = r[1];
                bh[2*ng+1][0] = r[2]; bh[2*ng+1][1] = r[3];
                ldmx4(r, blB + bo[2 * hf + ng][kk]);
                bl[2*ng][0] = r[0]; bl[2*ng][1] = r[1];
                bl[2*ng+1][0] = r[2]; bl[2*ng+1][1] = r[3];
            }
#pragma unroll
            for (int mt = 0; mt < 2; ++mt)
#pragma unroll
                for (int nt = 0; nt < 4; ++nt) {
                    mma16816(acc[mt][4*hf + nt], ah[mt], bh[nt]);
                    mma16816(acc[mt][4*hf + nt], ah[mt], bl[nt]);
                    mma16816(acc[mt][4*hf + nt], al[mt], bh[nt]);
                }
        }
    }
}

// ---------------------------------------------------------------------------
// bf16 GEMM, batched (z) + split-K (ks). C[z] = act(A[z] @ Wt[z]^T + bias[z]).
// 128x64 tile, BK=32, 4-stage ring, ONE sync/chunk, 2 CTAs/SM.
// Stage layout: Ah(8K) Al(8K) Bh(4K) Bl(4K) = 24KB.
// ---------------------------------------------------------------------------
#define G_AH 0
#define G_AL 8192
#define G_BH 16384
#define G_BL 20480
#define STAGE_BYTES 24576
#define GEMM_SMEM   (4 * STAGE_BYTES + 128)   // 98432

__global__ void __launch_bounds__(256, 2) gemm_bf16_kernel(
    const bf16* __restrict__ Ah, const bf16* __restrict__ Al,
    const bf16* __restrict__ Wh, const bf16* __restrict__ Wl,
    const float* __restrict__ bias,
    float* __restrict__ Cf, bf16* __restrict__ Ch, bf16* __restrict__ Cl,
    int N, int K, int relu, int ks, int pstr,
    int zsA, int zsW, int zsB, int zsC)
{
    extern __shared__ char smch[];
    const uint32_t base = (smem_u32(smch) + 127) & ~127u;

    const int z  = blockIdx.z / ks;
    const int kz = blockIdx.z % ks;
    const int Klocal = K / ks;
    const int kbase = kz * Klocal;

    Ah += (size_t)z * zsA;  Al += (size_t)z * zsA;
    Wh += (size_t)z * zsW;  Wl += (size_t)z * zsW;
    bias += (size_t)z * zsB;
    if (Cf) Cf += (size_t)z * zsC + (size_t)kz * pstr;
    if (Ch) { Ch += (size_t)z * zsC; Cl += (size_t)z * zsC; }

    const int tid  = threadIdx.x;
    const int lane = tid & 31;
    const int wid  = tid >> 5;
    const int wm   = wid & 3;           // m: 4 x 32
    const int wn   = wid >> 2;          // n: 2 x 32
    const int m0 = blockIdx.y * 128;
    const int n0 = blockIdx.x * 64;

    // per-thread cp.async descriptors: 6 x 16B chunks per stage (1536 total)
    const bf16* gsrc[6];
    uint32_t sdst[6];
#pragma unroll
    for (int it = 0; it < 6; ++it) {
        int c = tid + it * 256;
        int q = c & 3;
        const bf16* p;
        uint32_t off;
        if (c < 1024) {                       // A tiles: 128 rows
            int row = (c & 511) >> 2;
            p = (c < 512 ? Ah : Al) + (size_t)(m0 + row) * K;
            off = (c < 512 ? G_AH : G_AL) + swz(row * 64 + q * 16);
        } else {                              // B tiles: 64 rows
            int row = (c & 255) >> 2;
            p = (c < 1280 ? Wh : Wl) + (size_t)(n0 + row) * K;
            off = (c < 1280 ? G_BH : G_BL) + swz(row * 64 + q * 16);
        }
        gsrc[it] = p + kbase + q * 8;
        sdst[it] = off;
    }

    const int nch = Klocal >> 5;
    auto issue = [&](int s) {
        uint32_t st = base + (s & 3) * STAGE_BYTES;
#pragma unroll
        for (int it = 0; it < 6; ++it)
            cp16(st + sdst[it], gsrc[it] + s * 32);
    };
    // prologue: 3 groups (empty if s >= nch; commit regardless for accounting)
#pragma unroll
    for (int p = 0; p < 3; ++p) {
        if (p < nch) issue(p);
        CP_COMMIT;
    }

    const int aRow = wm * 32 + (lane & 15);
    const int aCol = (lane >> 4) * 8;
    const int bRow = wn * 32 + (lane & 7) + ((lane >> 4) << 3);
    const int bCol = ((lane >> 3) & 1) * 8;
    uint32_t a0[2], a1[2], bo[2][2];
#pragma unroll
    for (int kk = 0; kk < 2; ++kk) {
        a0[kk] = swz(aRow * 64 + aCol * 2 + kk * 32);
        a1[kk] = swz((aRow + 16) * 64 + aCol * 2 + kk * 32);
#pragma unroll
        for (int ng = 0; ng < 2; ++ng)
            bo[ng][kk] = swz((bRow + ng * 16) * 64 + bCol * 2 + kk * 32);
    }

    float acc[2][4][4] = {};

    for (int s = 0; s < nch; ++s) {
        CP_WAIT2;                 // groups <= s+... : stage s arrived
        __syncthreads();          // all warps done with stage s-1
        if (s + 3 < nch) issue(s + 3);   // -> buffer (s-1)&3, drained
        CP_COMMIT;
        uint32_t st = base + (s & 3) * STAGE_BYTES;
        tile_mma64(st + G_AH, st + G_AL, st + G_BH, st + G_BL,
                   a0, a1, bo, acc);
    }

    const int addb = (kz == 0);
#pragma unroll
    for (int mt = 0; mt < 2; ++mt) {
        int r0 = m0 + wm * 32 + mt * 16 + (lane >> 2);
#pragma unroll
        for (int nt = 0; nt < 4; ++nt) {
            int col = n0 + wn * 32 + nt * 8 + (lane & 3) * 2;
            float b0 = addb ? bias[col] : 0.f, b1 = addb ? bias[col + 1] : 0.f;
            float v0 = acc[mt][nt][0] + b0, v1 = acc[mt][nt][1] + b1;
            float v2 = acc[mt][nt][2] + b0, v3 = acc[mt][nt][3] + b1;
            if (relu) {
                v0 = fmaxf(v0, 0.f); v1 = fmaxf(v1, 0.f);
                v2 = fmaxf(v2, 0.f); v3 = fmaxf(v3, 0.f);
            }
            if (Ch) {
                uint32_t hh, ll;
                split2(v0, v1, hh, ll);
                *(uint32_t*)&Ch[(size_t)r0 * N + col] = hh;
                *(uint32_t*)&Cl[(size_t)r0 * N + col] = ll;
                split2(v2, v3, hh, ll);
                *(uint32_t*)&Ch[(size_t)(r0 + 8) * N + col] = hh;
                *(uint32_t*)&Cl[(size_t)(r0 + 8) * N + col] = ll;
            } else {
                *(float2*)&Cf[(size_t)r0 * N + col]       = make_float2(v0, v1);
                *(float2*)&Cf[(size_t)(r0 + 8) * N + col] = make_float2(v2, v3);
            }
        }
    }
}

// ---------------------------------------------------------------------------
// Relation tensor (R9 structure, unchanged): per block (b,i):
//   out[b,i,:,:] = ((sub_b * W_bi) @ obj_b^T)
// ---------------------------------------------------------------------------
#define RA_STAGE (2 * TILE_B)   // Ah, Al
#define RB_STAGE (2 * TILE_B)   // Bh, Bl
#define REL_SMEM (2048 + 2 * RA_STAGE + 3 * RB_STAGE + 128)  // 84096

__global__ void __launch_bounds__(256, 2) final_tc_kernel(
    const float* __restrict__ sub, const bf16* __restrict__ objh,
    const bf16* __restrict__ objl, const float* __restrict__ Wv,
    float* __restrict__ out)
{
    extern __shared__ char smch[];
    const uint32_t sb = (smem_u32(smch) + 127) & ~127u;
    float* ws = (float*)(smch + (sb - smem_u32(smch)));
    char* aPtr = (char*)ws + 2048;
    const uint32_t aBase = sb + 2048;
    const uint32_t bBase = aBase + 2 * RA_STAGE;

    const int i = blockIdx.x;
    const int b = blockIdx.y;
    const int tid  = threadIdx.x;
    const int lane = tid & 31;
    const int wid  = tid >> 5;
    const int wm   = wid & 3;
    const int wn   = wid >> 2;

    const float* wrow = Wv + (size_t)(b * SS + i) * DD;
    ws[tid]       = wrow[tid];
    ws[tid + 256] = wrow[tid + 256];

    const float* subB = sub + (size_t)b * SS * DD;
    const bf16* ohB = objh + (size_t)b * SS * DD;
    const bf16* olB = objl + (size_t)b * SS * DD;

    const bf16* bsrc[4];
    uint32_t bdst[4];
#pragma unroll
    for (int it = 0; it < 4; ++it) {
        int c = tid + it * 256;
        int a = c >> 9, idx = c & 511, row = idx >> 2, q = idx & 3;
        bsrc[it] = (a ? olB : ohB) + (size_t)row * DD + q * 8;
        bdst[it] = a * TILE_B + swz(row * 64 + q * 16);
    }
    int aLrow[4], aLc4[4];
#pragma unroll
    for (int it = 0; it < 4; ++it) {
        int idx = tid + it * 256;
        aLrow[it] = idx >> 3;
        aLc4[it]  = (idx & 7) << 2;
    }

    auto issueB = [&](int s) {
        uint32_t st = bBase + (s % 3) * RB_STAGE;
#pragma unroll
        for (int it = 0; it < 4; ++it)
            cp16(st + bdst[it], bsrc[it] + s * 32);
    };
    auto loadA = [&](int s, float4* r) {
#pragma unroll
        for (int it = 0; it < 4; ++it)
            r[it] = *(const float4*)&subB[(size_t)aLrow[it] * DD + s * 32 + aLc4[it]];
    };
    auto storeA = [&](int s, const float4* r) {
        char* dh = aPtr + (s & 1) * RA_STAGE;
        int kc = s * 32;
#pragma unroll
        for (int it = 0; it < 4; ++it) {
            float4 v = r[it];
            v.x *= ws[kc + aLc4[it]];     v.y *= ws[kc + aLc4[it] + 1];
            v.z *= ws[kc + aLc4[it] + 2]; v.w *= ws[kc + aLc4[it] + 3];
            uint32_t h0, h1, l0, l1;
            split2(v.x, v.y, h0, l0);
            split2(v.z, v.w, h1, l1);
            uint32_t off = swz(aLrow[it] * 64 + aLc4[it] * 2);
            *(uint2*)(dh + off)          = make_uint2(h0, h1);
            *(uint2*)(dh + TILE_B + off) = make_uint2(l0, l1);
        }
    };

    issueB(0); CP_COMMIT;
    issueB(1); CP_COMMIT;
    issueB(2); CP_COMMIT;
    __syncthreads();              // ws visible
    {
        float4 r0[4];
        loadA(0, r0);
        storeA(0, r0);
    }

    const int aRow = wm * 32 + (lane & 15);
    const int aCol = (lane >> 4) * 8;
    const int bRow = wn * 64 + (lane & 7) + ((lane >> 4) << 3);
    const int bCol = ((lane >> 3) & 1) * 8;
    uint32_t a0[2], a1[2], bo[4][2];
#pragma unroll
    for (int kk = 0; kk < 2; ++kk) {
        a0[kk] = swz(aRow * 64 + aCol * 2 + kk * 32);
        a1[kk] = swz((aRow + 16) * 64 + aCol * 2 + kk * 32);
#pragma unroll
        for (int ng = 0; ng < 4; ++ng)
            bo[ng][kk] = swz((bRow + ng * 16) * 64 + bCol * 2 + kk * 32);
    }

    float acc[2][8][4] = {};
    float4 pre[4];

    for (int s = 0; s < 16; ++s) {
        if (s + 1 < 16) loadA(s + 1, pre);
        CP_WAIT2;
        __syncthreads();
        uint32_t aB = aBase + (s & 1) * RA_STAGE;
        uint32_t bB = bBase + (s % 3) * RB_STAGE;
        tile_mma128(aB, aB + TILE_B, bB, bB + TILE_B, a0, a1, bo, acc);
        __syncthreads();
        if (s + 1 < 16) storeA(s + 1, pre);
        if (s + 3 < 16) issueB(s + 3);
        CP_COMMIT;
    }

    float* outB = out + (size_t)(b * SS + i) * SS * SS;
#pragma unroll
    for (int mt = 0; mt < 2; ++mt) {
        int r0 = wm * 32 + mt * 16 + (lane >> 2);
#pragma unroll
        for (int nt = 0; nt < 8; ++nt) {
            int col = wn * 64 + nt * 8 + (lane & 3) * 2;
            *(float2*)&outB[(size_t)r0 * SS + col] =
                make_float2(acc[mt][nt][0], acc[mt][nt][1]);
            *(float2*)&outB[(size_t)(r0 + 8) * SS + col] =
                make_float2(acc[mt][nt][2], acc[mt][nt][3]);
        }
    }
}

// ---------------------------------------------------------------------------
// Attention over axis L per (s, h); sums 2 qkv split-K partials; bf16 hi/lo out.
// ---------------------------------------------------------------------------
__global__ void attn_kernel(const float* __restrict__ qkv,
                            bf16* __restrict__ oh, bf16* __restrict__ ol)
{
    const int s = blockIdx.x;
    const int h = blockIdx.y;
    const int t = threadIdx.x;  // 0..63

    __shared__ float qs[8][65], ks[8][65], vs[8][65];
    __shared__ float at[8][9];

#pragma unroll
    for (int l = 0; l < 8; ++l) {
        size_t base = (size_t)(l * SS + s) * (3 * DD) + h * HDD + t;
        qs[l][t] = qkv[base]          + qkv[base + QPSTR];
        ks[l][t] = qkv[base + DD]     + qkv[base + DD + QPSTR];
        vs[l][t] = qkv[base + 2 * DD] + qkv[base + 2 * DD + QPSTR];
    }
    __syncthreads();

    const int l = t >> 3;
    const int m = t & 7;
    float sc = 0.0f;
#pragma unroll
    for (int d = 0; d < HDD; ++d) sc += qs[l][d] * ks[m][d];
    sc *= 0.125f;

    float mx = sc;
#pragma unroll
    for (int off = 1; off < 8; off <<= 1)
        mx = fmaxf(mx, __shfl_xor_sync(0xffffffffu, mx, off));
    float e = __expf(sc - mx);
    float sm = e;
#pragma unroll
    for (int off = 1; off < 8; off <<= 1)
        sm += __shfl_xor_sync(0xffffffffu, sm, off);
    at[l][m] = e / sm;
    __syncthreads();

    const int dg = (t & 7) * 8;
    float accv[8] = {};
#pragma unroll
    for (int mm = 0; mm < 8; ++mm) {
        float a = at[l][mm];
#pragma unroll
        for (int j = 0; j < 8; ++j)
            accv[j] = fmaf(a, vs[mm][dg + j], accv[j]);
    }
    size_t ob = (size_t)(l * SS + s) * DD + h * HDD + dg;
#pragma unroll
    for (int j = 0; j < 8; j += 2) {
        uint32_t hh, ll;
        split2(accv[j], accv[j + 1], hh, ll);
        *(uint32_t*)&oh[ob + j] = hh;
        *(uint32_t*)&ol[ob + j] = ll;
    }
}

// ---------------------------------------------------------------------------
// out = LayerNorm(a + sum_{p<np} P[p*pstr + .]); emits bf16 hi/lo if outh.
// ---------------------------------------------------------------------------
__global__ void add_ln_kernel(const float* __restrict__ a,
                              const float* __restrict__ P, int np, int pstr,
                              const float* __restrict__ gam, const float* __restrict__ bet,
                              float* __restrict__ out,
                              bf16* __restrict__ outh, bf16* __restrict__ outl)
{
    const int row = blockIdx.x;
    const int t = threadIdx.x;
    const size_t base = (size_t)row * DD;
    const int c = 2 * t;

    float v0 = a[base + c];
    float v1 = a[base + c + 1];
    for (int p = 0; p < np; ++p) {
        v0 += P[(size_t)p * pstr + base + c];
        v1 += P[(size_t)p * pstr + base + c + 1];
    }

    float s = v0 + v1;
    float q = v0 * v0 + v1 * v1;

    __shared__ float sred[16];
#pragma unroll
    for (int off = 16; off > 0; off >>= 1) {
        s += __shfl_xor_sync(0xffffffffu, s, off);
        q += __shfl_xor_sync(0xffffffffu, q, off);
    }
    if ((t & 31) == 0) { sred[t >> 5] = s; sred[(t >> 5) + 8] = q; }
    __syncthreads();
    if (t < 32) {
        float ss = (t < 8) ? sred[t] : 0.0f;
        float qq = (t < 8) ? sred[t + 8] : 0.0f;
#pragma unroll
        for (int off = 4; off > 0; off >>= 1) {
            ss += __shfl_xor_sync(0xffffffffu, ss, off);
            qq += __shfl_xor_sync(0xffffffffu, qq, off);
        }
        if (t == 0) { sred[0] = ss; sred[1] = qq; }
    }
    __syncthreads();

    const float mean = sred[0] * (1.0f / 512.0f);
    const float var  = sred[1] * (1.0f / 512.0f) - mean * mean;
    const float rstd = rsqrtf(var + 1e-5f);

    float y0 = (v0 - mean) * rstd * gam[c]     + bet[c];
    float y1 = (v1 - mean) * rstd * gam[c + 1] + bet[c + 1];
    *(float2*)&out[base + c] = make_float2(y0, y1);
    if (outh) {
        uint32_t hh, ll;
        split2(y0, y1, hh, ll);
        *(uint32_t*)&outh[base + c] = hh;
        *(uint32_t*)&outl[base + c] = ll;
    }
}

// ---------------------------------------------------------------------------
// Fused splitter: 8 segments of fp32 -> bf16 hi/lo (one launch).
// ---------------------------------------------------------------------------
struct SplitArgs {
    const float* src[8];
    bf16* dh[8];
    bf16* dl[8];
    int bstart[9];
};

__global__ void fused_split_kernel(SplitArgs sa)
{
    int blk = blockIdx.x;
    int seg = 0;
#pragma unroll
    for (int s = 1; s < 8; ++s) seg += (blk >= sa.bstart[s]);
    int idx = (blk - sa.bstart[seg]) * 256 + threadIdx.x;
    float4 x = ((const float4*)sa.src[seg])[idx];
    uint32_t h0, h1, l0, l1;
    split2(x.x, x.y, h0, l0);
    split2(x.z, x.w, h1, l1);
    ((uint2*)sa.dh[seg])[idx] = make_uint2(h0, h1);
    ((uint2*)sa.dl[seg])[idx] = make_uint2(l0, l1);
}

// ---------------------------------------------------------------------------
// Consumes 8 mlp2 split-K2 partial slabs (z-major pairs):
//   sub = P0+P1; obj = P2+P3 -> bf16 hi/lo; Wv = (P4+P5)*(P6+P7).
// ---------------------------------------------------------------------------
__global__ void mul_split_kernel(const float* __restrict__ P,
                                 float* __restrict__ subS, float* __restrict__ Wv,
                                 bf16* __restrict__ oh, bf16* __restrict__ ol)
{
    int i = blockIdx.x * blockDim.x + threadIdx.x;   // float4 index
    const float4* P4 = (const float4*)P;
    const int S4 = PSTR / 4;

    float4 s0 = P4[i], s1 = P4[i + S4];
    ((float4*)subS)[i] = make_float4(s0.x + s1.x, s0.y + s1.y,
                                     s0.z + s1.z, s0.w + s1.w);

    float4 o0 = P4[i + 2 * S4], o1 = P4[i + 3 * S4];
    float ox = o0.x + o1.x, oy = o0.y + o1.y, oz = o0.z + o1.z, ow = o0.w + o1.w;
    uint32_t h0, h1, l0, l1;
    split2(ox, oy, h0, l0);
    split2(oz, ow, h1, l1);
    ((uint2*)oh)[i] = make_uint2(h0, h1);
    ((uint2*)ol)[i] = make_uint2(l0, l1);

    float4 a0 = P4[i + 4 * S4], a1 = P4[i + 5 * S4];
    float4 b0 = P4[i + 6 * S4], b1 = P4[i + 7 * S4];
    ((float4*)Wv)[i] = make_float4((a0.x + a1.x) * (b0.x + b1.x),
                                   (a0.y + a1.y) * (b0.y + b1.y),
                                   (a0.z + a1.z) * (b0.z + b1.z),
                                   (a0.w + a1.w) * (b0.w + b1.w));
}

// ---------------------------------------------------------------------------
extern "C" void kernel_launch(void* const* d_in, const int* in_sizes, int n_in,
                              void* d_out, int out_size)
{
    const float* x   = (const float*)d_in[0];
    const float* aiw = (const float*)d_in[1];
    const float* aib = (const float*)d_in[2];
    const float* aow = (const float*)d_in[3];
    const float* aob = (const float*)d_in[4];
    const float* l1w = (const float*)d_in[5];
    const float* l1b = (const float*)d_in[6];
    const float* l2w = (const float*)d_in[7];
    const float* l2b = (const float*)d_in[8];
    const float* f1w = (const float*)d_in[9];
    const float* f1b = (const float*)d_in[10];
    const float* f2w = (const float*)d_in[11];
    const float* f2b = (const float*)d_in[12];
    const float* flw = (const float*)d_in[13];
    const float* flb = (const float*)d_in[14];
    const float* w0  = (const float*)d_in[15];
    const float* b0  = (const float*)d_in[16];
    const float* w1  = (const float*)d_in[17];
    const float* b1  = (const float*)d_in[18];
    const float* w2  = (const float*)d_in[19];
    const float* b2  = (const float*)d_in[20];
    float* out = (float*)d_out;

    bf16 *wh, *wl, *s0h, *s0l, *s1h, *s1l;
    float *h, *qkv, *part, *Wv, *subS;
    cudaGetSymbolAddress((void**)&wh,   g_wh);
    cudaGetSymbolAddress((void**)&wl,   g_wl);
    cudaGetSymbolAddress((void**)&s0h,  g_s0h);
    cudaGetSymbolAddress((void**)&s0l,  g_s0l);
    cudaGetSymbolAddress((void**)&s1h,  g_s1h);
    cudaGetSymbolAddress((void**)&s1l,  g_s1l);
    cudaGetSymbolAddress((void**)&h,    g_h);
    cudaGetSymbolAddress((void**)&qkv,  g_qkv);
    cudaGetSymbolAddress((void**)&part, g_part);
    cudaGetSymbolAddress((void**)&Wv,   g_Wv);
    cudaGetSymbolAddress((void**)&subS, g_sub);

    cudaFuncSetAttribute(gemm_bf16_kernel,
                         cudaFuncAttributeMaxDynamicSharedMemorySize, GEMM_SMEM);
    cudaFuncSetAttribute(final_tc_kernel,
                         cudaFuncAttributeMaxDynamicSharedMemorySize, REL_SMEM);

    // ---- launch 1: all splits fused (weights + x) ----
    {
        SplitArgs sa;
        sa.src[0] = aiw; sa.dh[0] = wh + OFF_AIW; sa.dl[0] = wl + OFF_AIW;
        sa.src[1] = aow; sa.dh[1] = wh + OFF_AOW; sa.dl[1] = wl + OFF_AOW;
        sa.src[2] = f1w; sa.dh[2] = wh + OFF_F1W; sa.dl[2] = wl + OFF_F1W;
        sa.src[3] = f2w; sa.dh[3] = wh + OFF_F2W; sa.dl[3] = wl + OFF_F2W;
        sa.src[4] = w0;  sa.dh[4] = wh + OFF_W0;  sa.dl[4] = wl + OFF_W0;
        sa.src[5] = w1;  sa.dh[5] = wh + OFF_W1;  sa.dl[5] = wl + OFF_W1;
        sa.src[6] = w2;  sa.dh[6] = wh + OFF_W2;  sa.dl[6] = wl + OFF_W2;
        sa.src[7] = x;   sa.dh[7] = s0h;          sa.dl[7] = s0l;
        int sizes[8] = {2359296, 786432, 3145728, 3145728,
                        1048576, 1048576, 1048576, 524288};
        int acc = 0;
        for (int s = 0; s < 8; ++s) { sa.bstart[s] = acc; acc += sizes[s] / 1024; }
        sa.bstart[8] = acc;
        fused_split_kernel<<<acc, 256>>>(sa);
    }

    // ---- encoder: 3 post-norm layers ----
    for (int i = 0; i < 3; ++i) {
        // qkv, split-K2 -> 2 partials in g_qkv : grid (24,8,2)=384
        gemm_bf16_kernel<<<dim3(24, 8, 2), 256, GEMM_SMEM>>>(
            s0h, s0l, wh + OFF_AIW + (size_t)i * 786432, wl + OFF_AIW + (size_t)i * 786432,
            aib + i * 1536, qkv, nullptr, nullptr, 1536, 512, 0, 2, QPSTR, 0, 0, 0, 0);

        attn_kernel<<<dim3(SS, HH), 64>>>(qkv, s1h, s1l);

        // attn-out, split-K4 (launch 4 on i=0: ncu slot): grid (8,8,4)=256
        gemm_bf16_kernel<<<dim3(8, 8, 4), 256, GEMM_SMEM>>>(
            s1h, s1l, wh + OFF_AOW + (size_t)i * 262144, wl + OFF_AOW + (size_t)i * 262144,
            aob + i * 512, part, nullptr, nullptr, 512, 512, 0, 4, PSTR, 0, 0, 0, 0);

        add_ln_kernel<<<NT, 256>>>((i == 0) ? x : h, part, 4, PSTR,
                                   l1w + i * 512, l1b + i * 512, h, s0h, s0l);

        // ff1 = relu(...) -> bf16 splits : grid (32,8)=256
        gemm_bf16_kernel<<<dim3(32, 8, 1), 256, GEMM_SMEM>>>(
            s0h, s0l, wh + OFF_F1W + (size_t)i * 1048576, wl + OFF_F1W + (size_t)i * 1048576,
            f1b + i * 2048, nullptr, s1h, s1l, 2048, 512, 1, 1, 0, 0, 0, 0, 0);

        // ff2, split-K8 : grid (8,8,8)=512
        gemm_bf16_kernel<<<dim3(8, 8, 8), 256, GEMM_SMEM>>>(
            s1h, s1l, wh + OFF_F2W + (size_t)i * 1048576, wl + OFF_F2W + (size_t)i * 1048576,
            f2b + i * 512, part, nullptr, nullptr, 512, 2048, 0, 8, PSTR, 0, 0, 0, 0);

        add_ln_kernel<<<NT, 256>>>(h, part, 8, PSTR,
                                   l2w + i * 512, l2b + i * 512, h, s0h, s0l);
    }

    // final encoder LN
    add_ln_kernel<<<NT, 256>>>(h, (const float*)nullptr, 0, 0, flw, flb, h, s0h, s0l);

    // ---- 4 projection MLPs, batched via blockIdx.z ----
    const int ZW = 262144, ZB = 512, ZC = NT * DD;
    gemm_bf16_kernel<<<dim3(8, 8, 4), 256, GEMM_SMEM>>>(
        s0h, s0l, wh + OFF_W0, wl + OFF_W0, b0, nullptr, s1h, s1l,
        512, 512, 1, 1, 0, 0, ZW, ZB, ZC);
    gemm_bf16_kernel<<<dim3(8, 8, 4), 256, GEMM_SMEM>>>(
        s1h, s1l, wh + OFF_W1, wl + OFF_W1, b1, nullptr, s0h, s0l,
        512, 512, 1, 1, 0, ZC, ZW, ZB, ZC);
    // mlp2: split-K2 per z -> 8 partial slabs (z-major pairs): grid (8,8,8)=512
    gemm_bf16_kernel<<<dim3(8, 8, 8), 256, GEMM_SMEM>>>(
        s0h, s0l, wh + OFF_W2, wl + OFF_W2, b2, part, nullptr, nullptr,
        512, 512, 0, 2, PSTR, ZC, ZW, ZB, 2 * PSTR);

    // sub/obj/vsub/vobj assembly + Wv + obj split
    mul_split_kernel<<<512, 256>>>(part, subS, Wv, s1h, s1l);

    // relation tensor: (8, 128, 128, 128) on tensor cores
    final_tc_kernel<<<dim3(SS, LL), 256, REL_SMEM>>>(subS, s1h, s1l, Wv, out);
}

// round 11
// speedup vs baseline: 1.1089x; 1.0183x over previous
#include <cuda_runtime.h>
#include <cuda_bf16.h>
#include <math.h>
#include <stdint.h>

// ---------------------------------------------------------------------------
// GraphDecoder on tensor cores (mma.sync bf16, 3-term hi/lo split, fp32 acc).
// Round 11 (GEMM kernel only; relation kernel = R9/R10 best):
//  - 64x64 tile, 128-thread CTAs, 3-stage ring (48KB) -> 4 CTAs/SM
//  - 4 independent warps per SMSP; 4-warp barrier domains
//  - split-K rebalance: qkv ks=1, attn-out ks=4, ff2 ks=4, mlp2 ks=1
// ---------------------------------------------------------------------------

#define LL  8
#define SS  128
#define DD  512
#define HH  8
#define HDD 64
#define NT  1024

typedef __nv_bfloat16 bf16;

// ---- persistent scratch ----------------------------------------------------
#define OFF_AIW 0            // 3 x 786432
#define OFF_AOW 2359296      // 3 x 262144
#define OFF_F1W 3145728      // 3 x 1048576
#define OFF_F2W 6291456      // 3 x 1048576
#define OFF_W0  9437184      // 4 x 262144
#define OFF_W1  10485760
#define OFF_W2  11534336
#define WTOT    12582912

#define PSTR  (NT * DD)           // 524288 floats per partial slab

__device__ bf16  g_wh[WTOT], g_wl[WTOT];
__device__ bf16  g_s0h[4 * NT * DD], g_s0l[4 * NT * DD];
__device__ bf16  g_s1h[4 * NT * DD], g_s1l[4 * NT * DD];
__device__ float g_h[NT * DD];
__device__ float g_qkv[NT * 3 * DD];
__device__ float g_part[8 * NT * DD];      // split-K / batch partial arena
__device__ float g_Wv[NT * DD];

// ========================= low-level helpers ================================
__device__ __forceinline__ uint32_t smem_u32(const void* p) {
    uint32_t a;
    asm("{ .reg .u64 t; cvta.to.shared.u64 t, %1; cvt.u32.u64 %0, t; }"
        : "=r"(a) : "l"(p));
    return a;
}

// swizzle for 64-byte rows: XOR bits [4:6) with bits [7:9)
__device__ __forceinline__ uint32_t swz(uint32_t off) {
    return off ^ (((off >> 7) & 3u) << 4);
}

__device__ __forceinline__ void ldmx4(uint32_t* r, uint32_t addr) {
    asm volatile("ldmatrix.sync.aligned.m8n8.x4.shared.b16 {%0,%1,%2,%3}, [%4];"
        : "=r"(r[0]), "=r"(r[1]), "=r"(r[2]), "=r"(r[3]) : "r"(addr));
}

__device__ __forceinline__ void mma16816(float* d, const uint32_t* a,
                                         const uint32_t* b) {
    asm volatile(
        "mma.sync.aligned.m16n8k16.row.col.f32.bf16.bf16.f32 "
        "{%0,%1,%2,%3}, {%4,%5,%6,%7}, {%8,%9}, {%0,%1,%2,%3};"
        : "+f"(d[0]), "+f"(d[1]), "+f"(d[2]), "+f"(d[3])
        : "r"(a[0]), "r"(a[1]), "r"(a[2]), "r"(a[3]), "r"(b[0]), "r"(b[1]));
}

__device__ __forceinline__ void cp16(uint32_t smem, const void* g) {
    asm volatile("cp.async.cg.shared.global [%0], [%1], 16;"
        :: "r"(smem), "l"(g));
}
#define CP_COMMIT asm volatile("cp.async.commit_group;" ::: "memory")
#define CP_WAIT1  asm volatile("cp.async.wait_group 1;" ::: "memory")
#define CP_WAIT2  asm volatile("cp.async.wait_group 2;" ::: "memory")

__device__ __forceinline__ void split2(float x, float y, uint32_t& hi, uint32_t& lo) {
    __nv_bfloat162 h, l;
    h.x = __float2bfloat16(x); h.y = __float2bfloat16(y);
    l.x = __float2bfloat16(x - __bfloat162float(h.x));
    l.y = __float2bfloat16(y - __bfloat162float(h.y));
    hi = *(uint32_t*)&h; lo = *(uint32_t*)&l;
}

#define TILE_B  8192   // 128x32 bf16 tile (relation kernel)
#define TILE64  4096   // 64x32 bf16 tile (gemm kernel)

// ---------------------------------------------------------------------------
// GEMM tile-mma (64x64, 4 warps 2m x 2n): A both-kk prefetch, term-outermost.
// acc[2][4][4] : mt 2 (2x16 m), nt 4 (4x8 = 32 n).
// ---------------------------------------------------------------------------
__device__ __forceinline__ void tile_mma44(
    uint32_t ahB, uint32_t alB, uint32_t bhB, uint32_t blB,
    const uint32_t* a0, const uint32_t* a1, const uint32_t (*bo)[2],
    float (&acc)[2][4][4])
{
    uint32_t ah[2][2][4], al[2][2][4];   // [kk][mt][4]
#pragma unroll
    for (int kk = 0; kk < 2; ++kk) {
        ldmx4(ah[kk][0], ahB + a0[kk]);
        ldmx4(ah[kk][1], ahB + a1[kk]);
        ldmx4(al[kk][0], alB + a0[kk]);
        ldmx4(al[kk][1], alB + a1[kk]);
    }
#pragma unroll
    for (int kk = 0; kk < 2; ++kk) {
        uint32_t bh[4][2], bl[4][2];
#pragma unroll
        for (int ng = 0; ng < 2; ++ng) {
            uint32_t r[4];
            ldmx4(r, bhB + bo[ng][kk]);
            bh[2*ng][0] = r[0]; bh[2*ng][1] = r[1];
            bh[2*ng+1][0] = r[2]; bh[2*ng+1][1] = r[3];
            ldmx4(r, blB + bo[ng][kk]);
            bl[2*ng][0] = r[0]; bl[2*ng][1] = r[1];
            bl[2*ng+1][0] = r[2]; bl[2*ng+1][1] = r[3];
        }
#pragma unroll
        for (int mt = 0; mt < 2; ++mt)
#pragma unroll
            for (int nt = 0; nt < 4; ++nt)
                mma16816(acc[mt][nt], ah[kk][mt], bh[nt]);
#pragma unroll
        for (int mt = 0; mt < 2; ++mt)
#pragma unroll
            for (int nt = 0; nt < 4; ++nt)
                mma16816(acc[mt][nt], ah[kk][mt], bl[nt]);
#pragma unroll
        for (int mt = 0; mt < 2; ++mt)
#pragma unroll
            for (int nt = 0; nt < 4; ++nt)
                mma16816(acc[mt][nt], al[kk][mt], bh[nt]);
    }
}

// ---------------------------------------------------------------------------
// Relation tile-mma (128x128): R9 form, acc[2][8][4].
// ---------------------------------------------------------------------------
__device__ __forceinline__ void tile_mma128(
    uint32_t ahB, uint32_t alB, uint32_t bhB, uint32_t blB,
    const uint32_t* a0, const uint32_t* a1, const uint32_t (*bo)[2],
    float (&acc)[2][8][4])
{
#pragma unroll
    for (int kk = 0; kk < 2; ++kk) {
        uint32_t ah[2][4], al[2][4];
        ldmx4(ah[0], ahB + a0[kk]);
        ldmx4(al[0], alB + a0[kk]);
        ldmx4(ah[1], ahB + a1[kk]);
        ldmx4(al[1], alB + a1[kk]);
#pragma unroll
        for (int hf = 0; hf < 2; ++hf) {
            uint32_t bh[4][2], bl[4][2];
#pragma unroll
            for (int ng = 0; ng < 2; ++ng) {
                uint32_t r[4];
                ldmx4(r, bhB + bo[2 * hf + ng][kk]);
                bh[2*ng][0] = r[0]; bh[2*ng][1] = r[1];
                bh[2*ng+1][0] = r[2]; bh[2*ng+1][1] = r[3];
                ldmx4(r, blB + bo[2 * hf + ng][kk]);
                bl[2*ng][0] = r[0]; bl[2*ng][1] = r[1];
                bl[2*ng+1][0] = r[2]; bl[2*ng+1][1] = r[3];
            }
#pragma unroll
            for (int mt = 0; mt < 2; ++mt)
#pragma unroll
                for (int nt = 0; nt < 4; ++nt) {
                    mma16816(acc[mt][4*hf + nt], ah[mt], bh[nt]);
                    mma16816(acc[mt][4*hf + nt], ah[mt], bl[nt]);
                    mma16816(acc[mt][4*hf + nt], al[mt], bh[nt]);
                }
        }
    }
}

// ---------------------------------------------------------------------------
// bf16 GEMM, batched (z) + split-K (ks). C[z] = act(A[z] @ Wt[z]^T + bias[z]).
// 64x64 tile, 128 threads, BK=32, 3-stage ring, ONE sync/chunk, 4 CTAs/SM.
// Stage: Ah(4K) Al(4K) Bh(4K) Bl(4K) = 16KB.
// ---------------------------------------------------------------------------
#define G_AH 0
#define G_AL 4096
#define G_BH 8192
#define G_BL 12288
#define STAGE_BYTES 16384
#define GEMM_SMEM   (3 * STAGE_BYTES + 128)   // 49280

__global__ void __launch_bounds__(128, 4) gemm_bf16_kernel(
    const bf16* __restrict__ Ah, const bf16* __restrict__ Al,
    const bf16* __restrict__ Wh, const bf16* __restrict__ Wl,
    const float* __restrict__ bias,
    float* __restrict__ Cf, bf16* __restrict__ Ch, bf16* __restrict__ Cl,
    int N, int K, int relu, int ks, int pstr,
    int zsA, int zsW, int zsB, int zsC)
{
    extern __shared__ char smch[];
    const uint32_t base = (smem_u32(smch) + 127) & ~127u;

    const int z  = blockIdx.z / ks;
    const int kz = blockIdx.z % ks;
    const int Klocal = K / ks;
    const int kbase = kz * Klocal;

    Ah += (size_t)z * zsA;  Al += (size_t)z * zsA;
    Wh += (size_t)z * zsW;  Wl += (size_t)z * zsW;
    bias += (size_t)z * zsB;
    if (Cf) Cf += (size_t)z * zsC + (size_t)kz * pstr;
    if (Ch) { Ch += (size_t)z * zsC; Cl += (size_t)z * zsC; }

    const int tid  = threadIdx.x;
    const int lane = tid & 31;
    const int wid  = tid >> 5;
    const int wm   = wid & 1;           // m: 2 x 32
    const int wn   = wid >> 1;          // n: 2 x 32
    const int m0 = blockIdx.y * 64;
    const int n0 = blockIdx.x * 64;

    // per-thread cp.async descriptors: 8 x 16B chunks per stage (1024 total)
    const bf16* gsrc[8];
    uint32_t sdst[8];
#pragma unroll
    for (int it = 0; it < 8; ++it) {
        int c = tid + it * 128;
        int a = c >> 8;             // 0..3 tile id
        int idx = c & 255;
        int row = idx >> 2;         // 0..63
        int q   = idx & 3;
        const bf16* p;
        if (a == 0)      p = Ah + (size_t)(m0 + row) * K;
        else if (a == 1) p = Al + (size_t)(m0 + row) * K;
        else if (a == 2) p = Wh + (size_t)(n0 + row) * K;
        else             p = Wl + (size_t)(n0 + row) * K;
        gsrc[it] = p + kbase + q * 8;
        sdst[it] = a * TILE64 + swz(row * 64 + q * 16);
    }

    const int nch = Klocal >> 5;
    auto issue = [&](int s) {
        uint32_t st = base + (s % 3) * STAGE_BYTES;
#pragma unroll
        for (int it = 0; it < 8; ++it)
            cp16(st + sdst[it], gsrc[it] + s * 32);
    };
    issue(0); CP_COMMIT;
    issue(1); CP_COMMIT;

    const int aRow = wm * 32 + (lane & 15);
    const int aCol = (lane >> 4) * 8;
    const int bRow = wn * 32 + (lane & 7) + ((lane >> 4) << 3);
    const int bCol = ((lane >> 3) & 1) * 8;
    uint32_t a0[2], a1[2], bo[2][2];
#pragma unroll
    for (int kk = 0; kk < 2; ++kk) {
        a0[kk] = swz(aRow * 64 + aCol * 2 + kk * 32);
        a1[kk] = swz((aRow + 16) * 64 + aCol * 2 + kk * 32);
#pragma unroll
        for (int ng = 0; ng < 2; ++ng)
            bo[ng][kk] = swz((bRow + ng * 16) * 64 + bCol * 2 + kk * 32);
    }

    float acc[2][4][4] = {};

    for (int s = 0; s < nch; ++s) {
        CP_WAIT1;                 // stage s arrived
        __syncthreads();          // 4 warps done with stage s-1
        if (s + 2 < nch) issue(s + 2);   // -> buffer (s-1)%3, drained
        CP_COMMIT;
        uint32_t st = base + (s % 3) * STAGE_BYTES;
        tile_mma44(st + G_AH, st + G_AL, st + G_BH, st + G_BL,
                   a0, a1, bo, acc);
    }

    const int addb = (kz == 0);
#pragma unroll
    for (int mt = 0; mt < 2; ++mt) {
        int r0 = m0 + wm * 32 + mt * 16 + (lane >> 2);
#pragma unroll
        for (int nt = 0; nt < 4; ++nt) {
            int col = n0 + wn * 32 + nt * 8 + (lane & 3) * 2;
            float b0 = addb ? bias[col] : 0.f, b1 = addb ? bias[col + 1] : 0.f;
            float v0 = acc[mt][nt][0] + b0, v1 = acc[mt][nt][1] + b1;
            float v2 = acc[mt][nt][2] + b0, v3 = acc[mt][nt][3] + b1;
            if (relu) {
                v0 = fmaxf(v0, 0.f); v1 = fmaxf(v1, 0.f);
                v2 = fmaxf(v2, 0.f); v3 = fmaxf(v3, 0.f);
            }
            if (Ch) {
                uint32_t hh, ll;
                split2(v0, v1, hh, ll);
                *(uint32_t*)&Ch[(size_t)r0 * N + col] = hh;
                *(uint32_t*)&Cl[(size_t)r0 * N + col] = ll;
                split2(v2, v3, hh, ll);
                *(uint32_t*)&Ch[(size_t)(r0 + 8) * N + col] = hh;
                *(uint32_t*)&Cl[(size_t)(r0 + 8) * N + col] = ll;
            } else {
                *(float2*)&Cf[(size_t)r0 * N + col]       = make_float2(v0, v1);
                *(float2*)&Cf[(size_t)(r0 + 8) * N + col] = make_float2(v2, v3);
            }
        }
    }
}

// ---------------------------------------------------------------------------
// Relation tensor (R9 structure, unchanged).
// ---------------------------------------------------------------------------
#define RA_STAGE (2 * TILE_B)
#define RB_STAGE (2 * TILE_B)
#define REL_SMEM (2048 + 2 * RA_STAGE + 3 * RB_STAGE + 128)  // 84096

__global__ void __launch_bounds__(256, 2) final_tc_kernel(
    const float* __restrict__ sub, const bf16* __restrict__ objh,
    const bf16* __restrict__ objl, const float* __restrict__ Wv,
    float* __restrict__ out)
{
    extern __shared__ char smch[];
    const uint32_t sb = (smem_u32(smch) + 127) & ~127u;
    float* ws = (float*)(smch + (sb - smem_u32(smch)));
    char* aPtr = (char*)ws + 2048;
    const uint32_t aBase = sb + 2048;
    const uint32_t bBase = aBase + 2 * RA_STAGE;

    const int i = blockIdx.x;
    const int b = blockIdx.y;
    const int tid  = threadIdx.x;
    const int lane = tid & 31;
    const int wid  = tid >> 5;
    const int wm   = wid & 3;
    const int wn   = wid >> 2;

    const float* wrow = Wv + (size_t)(b * SS + i) * DD;
    ws[tid]       = wrow[tid];
    ws[tid + 256] = wrow[tid + 256];

    const float* subB = sub + (size_t)b * SS * DD;
    const bf16* ohB = objh + (size_t)b * SS * DD;
    const bf16* olB = objl + (size_t)b * SS * DD;

    const bf16* bsrc[4];
    uint32_t bdst[4];
#pragma unroll
    for (int it = 0; it < 4; ++it) {
        int c = tid + it * 256;
        int a = c >> 9, idx = c & 511, row = idx >> 2, q = idx & 3;
        bsrc[it] = (a ? olB : ohB) + (size_t)row * DD + q * 8;
        bdst[it] = a * TILE_B + swz(row * 64 + q * 16);
    }
    int aLrow[4], aLc4[4];
#pragma unroll
    for (int it = 0; it < 4; ++it) {
        int idx = tid + it * 256;
        aLrow[it] = idx >> 3;
        aLc4[it]  = (idx & 7) << 2;
    }

    auto issueB = [&](int s) {
        uint32_t st = bBase + (s % 3) * RB_STAGE;
#pragma unroll
        for (int it = 0; it < 4; ++it)
            cp16(st + bdst[it], bsrc[it] + s * 32);
    };
    auto loadA = [&](int s, float4* r) {
#pragma unroll
        for (int it = 0; it < 4; ++it)
            r[it] = *(const float4*)&subB[(size_t)aLrow[it] * DD + s * 32 + aLc4[it]];
    };
    auto storeA = [&](int s, const float4* r) {
        char* dh = aPtr + (s & 1) * RA_STAGE;
        int kc = s * 32;
#pragma unroll
        for (int it = 0; it < 4; ++it) {
            float4 v = r[it];
            v.x *= ws[kc + aLc4[it]];     v.y *= ws[kc + aLc4[it] + 1];
            v.z *= ws[kc + aLc4[it] + 2]; v.w *= ws[kc + aLc4[it] + 3];
            uint32_t h0, h1, l0, l1;
            split2(v.x, v.y, h0, l0);
            split2(v.z, v.w, h1, l1);
            uint32_t off = swz(aLrow[it] * 64 + aLc4[it] * 2);
            *(uint2*)(dh + off)          = make_uint2(h0, h1);
            *(uint2*)(dh + TILE_B + off) = make_uint2(l0, l1);
        }
    };

    issueB(0); CP_COMMIT;
    issueB(1); CP_COMMIT;
    issueB(2); CP_COMMIT;
    __syncthreads();              // ws visible
    {
        float4 r0[4];
        loadA(0, r0);
        storeA(0, r0);
    }

    const int aRow = wm * 32 + (lane & 15);
    const int aCol = (lane >> 4) * 8;
    const int bRow = wn * 64 + (lane & 7) + ((lane >> 4) << 3);
    const int bCol = ((lane >> 3) & 1) * 8;
    uint32_t a0[2], a1[2], bo[4][2];
#pragma unroll
    for (int kk = 0; kk < 2; ++kk) {
        a0[kk] = swz(aRow * 64 + aCol * 2 + kk * 32);
        a1[kk] = swz((aRow + 16) * 64 + aCol * 2 + kk * 32);
#pragma unroll
        for (int ng = 0; ng < 4; ++ng)
            bo[ng][kk] = swz((bRow + ng * 16) * 64 + bCol * 2 + kk * 32);
    }

    float acc[2][8][4] = {};
    float4 pre[4];

    for (int s = 0; s < 16; ++s) {
        if (s + 1 < 16) loadA(s + 1, pre);
        CP_WAIT2;
        __syncthreads();
        uint32_t aB = aBase + (s & 1) * RA_STAGE;
        uint32_t bB = bBase + (s % 3) * RB_STAGE;
        tile_mma128(aB, aB + TILE_B, bB, bB + TILE_B, a0, a1, bo, acc);
        __syncthreads();
        if (s + 1 < 16) storeA(s + 1, pre);
        if (s + 3 < 16) issueB(s + 3);
        CP_COMMIT;
    }

    float* outB = out + (size_t)(b * SS + i) * SS * SS;
#pragma unroll
    for (int mt = 0; mt < 2; ++mt) {
        int r0 = wm * 32 + mt * 16 + (lane >> 2);
#pragma unroll
        for (int nt = 0; nt < 8; ++nt) {
            int col = wn * 64 + nt * 8 + (lane & 3) * 2;
            *(float2*)&outB[(size_t)r0 * SS + col] =
                make_float2(acc[mt][nt][0], acc[mt][nt][1]);
            *(float2*)&outB[(size_t)(r0 + 8) * SS + col] =
                make_float2(acc[mt][nt][2], acc[mt][nt][3]);
        }
    }
}

// ---------------------------------------------------------------------------
// Attention over axis L per (s, h); single qkv buffer; bf16 hi/lo out.
// ---------------------------------------------------------------------------
__global__ void attn_kernel(const float* __restrict__ qkv,
                            bf16* __restrict__ oh, bf16* __restrict__ ol)
{
    const int s = blockIdx.x;
    const int h = blockIdx.y;
    const int t = threadIdx.x;  // 0..63

    __shared__ float qs[8][65], ks[8][65], vs[8][65];
    __shared__ float at[8][9];

#pragma unroll
    for (int l = 0; l < 8; ++l) {
        size_t base = (size_t)(l * SS + s) * (3 * DD) + h * HDD + t;
        qs[l][t] = qkv[base];
        ks[l][t] = qkv[base + DD];
        vs[l][t] = qkv[base + 2 * DD];
    }
    __syncthreads();

    const int l = t >> 3;
    const int m = t & 7;
    float sc = 0.0f;
#pragma unroll
    for (int d = 0; d < HDD; ++d) sc += qs[l][d] * ks[m][d];
    sc *= 0.125f;

    float mx = sc;
#pragma unroll
    for (int off = 1; off < 8; off <<= 1)
        mx = fmaxf(mx, __shfl_xor_sync(0xffffffffu, mx, off));
    float e = __expf(sc - mx);
    float sm = e;
#pragma unroll
    for (int off = 1; off < 8; off <<= 1)
        sm += __shfl_xor_sync(0xffffffffu, sm, off);
    at[l][m] = e / sm;
    __syncthreads();

    const int dg = (t & 7) * 8;
    float accv[8] = {};
#pragma unroll
    for (int mm = 0; mm < 8; ++mm) {
        float a = at[l][mm];
#pragma unroll
        for (int j = 0; j < 8; ++j)
            accv[j] = fmaf(a, vs[mm][dg + j], accv[j]);
    }
    size_t ob = (size_t)(l * SS + s) * DD + h * HDD + dg;
#pragma unroll
    for (int j = 0; j < 8; j += 2) {
        uint32_t hh, ll;
        split2(accv[j], accv[j + 1], hh, ll);
        *(uint32_t*)&oh[ob + j] = hh;
        *(uint32_t*)&ol[ob + j] = ll;
    }
}

// ---------------------------------------------------------------------------
// out = LayerNorm(a + sum_{p<np} P[p*pstr + .]); emits bf16 hi/lo if outh.
// ---------------------------------------------------------------------------
__global__ void add_ln_kernel(const float* __restrict__ a,
                              const float* __restrict__ P, int np, int pstr,
                              const float* __restrict__ gam, const float* __restrict__ bet,
                              float* __restrict__ out,
                              bf16* __restrict__ outh, bf16* __restrict__ outl)
{
    const int row = blockIdx.x;
    const int t = threadIdx.x;
    const size_t base = (size_t)row * DD;
    const int c = 2 * t;

    float v0 = a[base + c];
    float v1 = a[base + c + 1];
    for (int p = 0; p < np; ++p) {
        v0 += P[(size_t)p * pstr + base + c];
        v1 += P[(size_t)p * pstr + base + c + 1];
    }

    float s = v0 + v1;
    float q = v0 * v0 + v1 * v1;

    __shared__ float sred[16];
#pragma unroll
    for (int off = 16; off > 0; off >>= 1) {
        s += __shfl_xor_sync(0xffffffffu, s, off);
        q += __shfl_xor_sync(0xffffffffu, q, off);
    }
    if ((t & 31) == 0) { sred[t >> 5] = s; sred[(t >> 5) + 8] = q; }
    __syncthreads();
    if (t < 32) {
        float ss = (t < 8) ? sred[t] : 0.0f;
        float qq = (t < 8) ? sred[t + 8] : 0.0f;
#pragma unroll
        for (int off = 4; off > 0; off >>= 1) {
            ss += __shfl_xor_sync(0xffffffffu, ss, off);
            qq += __shfl_xor_sync(0xffffffffu, qq, off);
        }
        if (t == 0) { sred[0] = ss; sred[1] = qq; }
    }
    __syncthreads();

    const float mean = sred[0] * (1.0f / 512.0f);
    const float var  = sred[1] * (1.0f / 512.0f) - mean * mean;
    const float rstd = rsqrtf(var + 1e-5f);

    float y0 = (v0 - mean) * rstd * gam[c]     + bet[c];
    float y1 = (v1 - mean) * rstd * gam[c + 1] + bet[c + 1];
    *(float2*)&out[base + c] = make_float2(y0, y1);
    if (outh) {
        uint32_t hh, ll;
        split2(y0, y1, hh, ll);
        *(uint32_t*)&outh[base + c] = hh;
        *(uint32_t*)&outl[base + c] = ll;
    }
}

// ---------------------------------------------------------------------------
// Fused splitter: 8 segments of fp32 -> bf16 hi/lo (one launch).
// ---------------------------------------------------------------------------
struct SplitArgs {
    const float* src[8];
    bf16* dh[8];
    bf16* dl[8];
    int bstart[9];
};

__global__ void fused_split_kernel(SplitArgs sa)
{
    int blk = blockIdx.x;
    int seg = 0;
#pragma unroll
    for (int s = 1; s < 8; ++s) seg += (blk >= sa.bstart[s]);
    int idx = (blk - sa.bstart[seg]) * 256 + threadIdx.x;
    float4 x = ((const float4*)sa.src[seg])[idx];
    uint32_t h0, h1, l0, l1;
    split2(x.x, x.y, h0, l0);
    split2(x.z, x.w, h1, l1);
    ((uint2*)sa.dh[seg])[idx] = make_uint2(h0, h1);
    ((uint2*)sa.dl[seg])[idx] = make_uint2(l0, l1);
}

// ---------------------------------------------------------------------------
// Consumes 4 mlp2 batch slabs: obj = P1 -> bf16 hi/lo; Wv = P2 * P3.
// (sub = P0 is consumed directly by final_tc_kernel.)
// ---------------------------------------------------------------------------
__global__ void mul_split_kernel(const float* __restrict__ P,
                                 float* __restrict__ Wv,
                                 bf16* __restrict__ oh, bf16* __restrict__ ol)
{
    int i = blockIdx.x * blockDim.x + threadIdx.x;   // float4 index
    const float4* P4 = (const float4*)P;
    const int S4 = PSTR / 4;

    float4 o = P4[i + S4];
    uint32_t h0, h1, l0, l1;
    split2(o.x, o.y, h0, l0);
    split2(o.z, o.w, h1, l1);
    ((uint2*)oh)[i] = make_uint2(h0, h1);
    ((uint2*)ol)[i] = make_uint2(l0, l1);

    float4 a = P4[i + 2 * S4];
    float4 b = P4[i + 3 * S4];
    ((float4*)Wv)[i] = make_float4(a.x * b.x, a.y * b.y, a.z * b.z, a.w * b.w);
}

// ---------------------------------------------------------------------------
extern "C" void kernel_launch(void* const* d_in, const int* in_sizes, int n_in,
                              void* d_out, int out_size)
{
    const float* x   = (const float*)d_in[0];
    const float* aiw = (const float*)d_in[1];
    const float* aib = (const float*)d_in[2];
    const float* aow = (const float*)d_in[3];
    const float* aob = (const float*)d_in[4];
    const float* l1w = (const float*)d_in[5];
    const float* l1b = (const float*)d_in[6];
    const float* l2w = (const float*)d_in[7];
    const float* l2b = (const float*)d_in[8];
    const float* f1w = (const float*)d_in[9];
    const float* f1b = (const float*)d_in[10];
    const float* f2w = (const float*)d_in[11];
    const float* f2b = (const float*)d_in[12];
    const float* flw = (const float*)d_in[13];
    const float* flb = (const float*)d_in[14];
    const float* w0  = (const float*)d_in[15];
    const float* b0  = (const float*)d_in[16];
    const float* w1  = (const float*)d_in[17];
    const float* b1  = (const float*)d_in[18];
    const float* w2  = (const float*)d_in[19];
    const float* b2  = (const float*)d_in[20];
    float* out = (float*)d_out;

    bf16 *wh, *wl, *s0h, *s0l, *s1h, *s1l;
    float *h, *qkv, *part, *Wv;
    cudaGetSymbolAddress((void**)&wh,   g_wh);
    cudaGetSymbolAddress((void**)&wl,   g_wl);
    cudaGetSymbolAddress((void**)&s0h,  g_s0h);
    cudaGetSymbolAddress((void**)&s0l,  g_s0l);
    cudaGetSymbolAddress((void**)&s1h,  g_s1h);
    cudaGetSymbolAddress((void**)&s1l,  g_s1l);
    cudaGetSymbolAddress((void**)&h,    g_h);
    cudaGetSymbolAddress((void**)&qkv,  g_qkv);
    cudaGetSymbolAddress((void**)&part, g_part);
    cudaGetSymbolAddress((void**)&Wv,   g_Wv);

    cudaFuncSetAttribute(gemm_bf16_kernel,
                         cudaFuncAttributeMaxDynamicSharedMemorySize, GEMM_SMEM);
    cudaFuncSetAttribute(final_tc_kernel,
                         cudaFuncAttributeMaxDynamicSharedMemorySize, REL_SMEM);

    // ---- launch 1: all splits fused (weights + x) ----
    {
        SplitArgs sa;
        sa.src[0] = aiw; sa.dh[0] = wh + OFF_AIW; sa.dl[0] = wl + OFF_AIW;
        sa.src[1] = aow; sa.dh[1] = wh + OFF_AOW; sa.dl[1] = wl + OFF_AOW;
        sa.src[2] = f1w; sa.dh[2] = wh + OFF_F1W; sa.dl[2] = wl + OFF_F1W;
        sa.src[3] = f2w; sa.dh[3] = wh + OFF_F2W; sa.dl[3] = wl + OFF_F2W;
        sa.src[4] = w0;  sa.dh[4] = wh + OFF_W0;  sa.dl[4] = wl + OFF_W0;
        sa.src[5] = w1;  sa.dh[5] = wh + OFF_W1;  sa.dl[5] = wl + OFF_W1;
        sa.src[6] = w2;  sa.dh[6] = wh + OFF_W2;  sa.dl[6] = wl + OFF_W2;
        sa.src[7] = x;   sa.dh[7] = s0h;          sa.dl[7] = s0l;
        int sizes[8] = {2359296, 786432, 3145728, 3145728,
                        1048576, 1048576, 1048576, 524288};
        int acc = 0;
        for (int s = 0; s < 8; ++s) { sa.bstart[s] = acc; acc += sizes[s] / 1024; }
        sa.bstart[8] = acc;
        fused_split_kernel<<<acc, 256>>>(sa);
    }

    // ---- encoder: 3 post-norm layers ----
    for (int i = 0; i < 3; ++i) {
        // qkv: grid (24,16,1)=384 CTAs, 16 chunks each
        gemm_bf16_kernel<<<dim3(24, 16, 1), 128, GEMM_SMEM>>>(
            s0h, s0l, wh + OFF_AIW + (size_t)i * 786432, wl + OFF_AIW + (size_t)i * 786432,
            aib + i * 1536, qkv, nullptr, nullptr, 1536, 512, 0, 1, 0, 0, 0, 0, 0);

        attn_kernel<<<dim3(SS, HH), 64>>>(qkv, s1h, s1l);

        // attn-out, split-K4 (launch 4 on i=0: ncu slot): grid (8,16,4)=512
        gemm_bf16_kernel<<<dim3(8, 16, 4), 128, GEMM_SMEM>>>(
            s1h, s1l, wh + OFF_AOW + (size_t)i * 262144, wl + OFF_AOW + (size_t)i * 262144,
            aob + i * 512, part, nullptr, nullptr, 512, 512, 0, 4, PSTR, 0, 0, 0, 0);

        add_ln_kernel<<<NT, 256>>>((i == 0) ? x : h, part, 4, PSTR,
                                   l1w + i * 512, l1b + i * 512, h, s0h, s0l);

        // ff1 = relu(...) -> bf16 splits : grid (32,16)=512
        gemm_bf16_kernel<<<dim3(32, 16, 1), 128, GEMM_SMEM>>>(
            s0h, s0l, wh + OFF_F1W + (size_t)i * 1048576, wl + OFF_F1W + (size_t)i * 1048576,
            f1b + i * 2048, nullptr, s1h, s1l, 2048, 512, 1, 1, 0, 0, 0, 0, 0);

        // ff2, split-K4 : grid (8,16,4)=512, 16 chunks
        gemm_bf16_kernel<<<dim3(8, 16, 4), 128, GEMM_SMEM>>>(
            s1h, s1l, wh + OFF_F2W + (size_t)i * 1048576, wl + OFF_F2W + (size_t)i * 1048576,
            f2b + i * 512, part, nullptr, nullptr, 512, 2048, 0, 4, PSTR, 0, 0, 0, 0);

        add_ln_kernel<<<NT, 256>>>(h, part, 4, PSTR,
                                   l2w + i * 512, l2b + i * 512, h, s0h, s0l);
    }

    // final encoder LN
    add_ln_kernel<<<NT, 256>>>(h, (const float*)nullptr, 0, 0, flw, flb, h, s0h, s0l);

    // ---- 4 projection MLPs, batched via blockIdx.z ----
    const int ZW = 262144, ZB = 512, ZC = NT * DD;
    gemm_bf16_kernel<<<dim3(8, 16, 4), 128, GEMM_SMEM>>>(
        s0h, s0l, wh + OFF_W0, wl + OFF_W0, b0, nullptr, s1h, s1l,
        512, 512, 1, 1, 0, 0, ZW, ZB, ZC);
    gemm_bf16_kernel<<<dim3(8, 16, 4), 128, GEMM_SMEM>>>(
        s1h, s1l, wh + OFF_W1, wl + OFF_W1, b1, nullptr, s0h, s0l,
        512, 512, 1, 1, 0, ZC, ZW, ZB, ZC);
    // mlp2: 4 z-batched fp32 outputs -> part slabs [sub|obj|vsub|vobj]
    gemm_bf16_kernel<<<dim3(8, 16, 4), 128, GEMM_SMEM>>>(
        s0h, s0l, wh + OFF_W2, wl + OFF_W2, b2, part, nullptr, nullptr,
        512, 512, 0, 1, 0, ZC, ZW, ZB, PSTR);

    // obj -> bf16 hi/lo; Wv = vsub*vobj (sub used in place from part)
    mul_split_kernel<<<512, 256>>>(part, Wv, s1h, s1l);

    // relation tensor: (8, 128, 128, 128) on tensor cores
    final_tc_kernel<<<dim3(SS, LL), 256, REL_SMEM>>>(part, s1h, s1l, Wv, out);
}

// round 12
// speedup vs baseline: 1.3023x; 1.1744x over previous
#include <cuda_runtime.h>
#include <cuda_fp16.h>
#include <math.h>
#include <stdint.h>

// ---------------------------------------------------------------------------
// GraphDecoder on tensor cores (mma.sync fp16, hi/lo split, fp32 acc).
// Round 12: bf16 -> fp16 (half-ulp 2^-11 vs 2^-8).
//  - encoder/MLP GEMMs: fp16 3-term (chain error ~1e-6, was 2.5e-5)
//  - relation kernel: SINGLE-term fp16 (error ~4e-4, last op, no chain)
//    -> relation MMA work 51.5 -> 17.2 GF (~100us saved at the ~330TF/s
//       legacy-HMMA ceiling we are now pinned against)
// ---------------------------------------------------------------------------

#define LL  8
#define SS  128
#define DD  512
#define HH  8
#define HDD 64
#define NT  1024

typedef __half f16;

// ---- persistent scratch ----------------------------------------------------
#define OFF_AIW 0            // 3 x 786432
#define OFF_AOW 2359296      // 3 x 262144
#define OFF_F1W 3145728      // 3 x 1048576
#define OFF_F2W 6291456      // 3 x 1048576
#define OFF_W0  9437184      // 4 x 262144
#define OFF_W1  10485760
#define OFF_W2  11534336
#define WTOT    12582912

#define PSTR  (NT * DD)           // 524288 floats per partial slab

__device__ f16   g_wh[WTOT], g_wl[WTOT];
__device__ f16   g_s0h[4 * NT * DD], g_s0l[4 * NT * DD];
__device__ f16   g_s1h[4 * NT * DD], g_s1l[4 * NT * DD];
__device__ float g_h[NT * DD];
__device__ float g_qkv[NT * 3 * DD];
__device__ float g_part[8 * NT * DD];      // split-K / batch partial arena
__device__ float g_Wv[NT * DD];

// ========================= low-level helpers ================================
__device__ __forceinline__ uint32_t smem_u32(const void* p) {
    uint32_t a;
    asm("{ .reg .u64 t; cvta.to.shared.u64 t, %1; cvt.u32.u64 %0, t; }"
        : "=r"(a) : "l"(p));
    return a;
}

// swizzle for 64-byte rows: XOR bits [4:6) with bits [7:9)
__device__ __forceinline__ uint32_t swz(uint32_t off) {
    return off ^ (((off >> 7) & 3u) << 4);
}

__device__ __forceinline__ void ldmx4(uint32_t* r, uint32_t addr) {
    asm volatile("ldmatrix.sync.aligned.m8n8.x4.shared.b16 {%0,%1,%2,%3}, [%4];"
        : "=r"(r[0]), "=r"(r[1]), "=r"(r[2]), "=r"(r[3]) : "r"(addr));
}

__device__ __forceinline__ void mma16816(float* d, const uint32_t* a,
                                         const uint32_t* b) {
    asm volatile(
        "mma.sync.aligned.m16n8k16.row.col.f32.f16.f16.f32 "
        "{%0,%1,%2,%3}, {%4,%5,%6,%7}, {%8,%9}, {%0,%1,%2,%3};"
        : "+f"(d[0]), "+f"(d[1]), "+f"(d[2]), "+f"(d[3])
        : "r"(a[0]), "r"(a[1]), "r"(a[2]), "r"(a[3]), "r"(b[0]), "r"(b[1]));
}

__device__ __forceinline__ void cp16(uint32_t smem, const void* g) {
    asm volatile("cp.async.cg.shared.global [%0], [%1], 16;"
        :: "r"(smem), "l"(g));
}
#define CP_COMMIT asm volatile("cp.async.commit_group;" ::: "memory")
#define CP_WAIT1  asm volatile("cp.async.wait_group 1;" ::: "memory")
#define CP_WAIT2  asm volatile("cp.async.wait_group 2;" ::: "memory")

__device__ __forceinline__ void split2(float x, float y, uint32_t& hi, uint32_t& lo) {
    __half2 h, l;
    h.x = __float2half(x); h.y = __float2half(y);
    l.x = __float2half(x - __half2float(h.x));
    l.y = __float2half(y - __half2float(h.y));
    hi = *(uint32_t*)&h; lo = *(uint32_t*)&l;
}

__device__ __forceinline__ uint32_t pack2(float x, float y) {
    __half2 h;
    h.x = __float2half(x); h.y = __float2half(y);
    return *(uint32_t*)&h;
}

#define TILE_B  8192   // 128x32 f16 tile
#define TILE64  4096   // 64x32 f16 tile

// ---------------------------------------------------------------------------
// GEMM tile-mma (64x64, 4 warps 2m x 2n): A both-kk prefetch, term-outermost.
// ---------------------------------------------------------------------------
__device__ __forceinline__ void tile_mma44(
    uint32_t ahB, uint32_t alB, uint32_t bhB, uint32_t blB,
    const uint32_t* a0, const uint32_t* a1, const uint32_t (*bo)[2],
    float (&acc)[2][4][4])
{
    uint32_t ah[2][2][4], al[2][2][4];   // [kk][mt][4]
#pragma unroll
    for (int kk = 0; kk < 2; ++kk) {
        ldmx4(ah[kk][0], ahB + a0[kk]);
        ldmx4(ah[kk][1], ahB + a1[kk]);
        ldmx4(al[kk][0], alB + a0[kk]);
        ldmx4(al[kk][1], alB + a1[kk]);
    }
#pragma unroll
    for (int kk = 0; kk < 2; ++kk) {
        uint32_t bh[4][2], bl[4][2];
#pragma unroll
        for (int ng = 0; ng < 2; ++ng) {
            uint32_t r[4];
            ldmx4(r, bhB + bo[ng][kk]);
            bh[2*ng][0] = r[0]; bh[2*ng][1] = r[1];
            bh[2*ng+1][0] = r[2]; bh[2*ng+1][1] = r[3];
            ldmx4(r, blB + bo[ng][kk]);
            bl[2*ng][0] = r[0]; bl[2*ng][1] = r[1];
            bl[2*ng+1][0] = r[2]; bl[2*ng+1][1] = r[3];
        }
#pragma unroll
        for (int mt = 0; mt < 2; ++mt)
#pragma unroll
            for (int nt = 0; nt < 4; ++nt)
                mma16816(acc[mt][nt], ah[kk][mt], bh[nt]);
#pragma unroll
        for (int mt = 0; mt < 2; ++mt)
#pragma unroll
            for (int nt = 0; nt < 4; ++nt)
                mma16816(acc[mt][nt], ah[kk][mt], bl[nt]);
#pragma unroll
        for (int mt = 0; mt < 2; ++mt)
#pragma unroll
            for (int nt = 0; nt < 4; ++nt)
                mma16816(acc[mt][nt], al[kk][mt], bh[nt]);
    }
}

// ---------------------------------------------------------------------------
// Relation tile-mma (128x128, SINGLE term): acc[2][8][4].
// ---------------------------------------------------------------------------
__device__ __forceinline__ void tile_mma_rel(
    uint32_t ahB, uint32_t bhB,
    const uint32_t* a0, const uint32_t* a1, const uint32_t (*bo)[2],
    float (&acc)[2][8][4])
{
#pragma unroll
    for (int kk = 0; kk < 2; ++kk) {
        uint32_t ah[2][4];
        ldmx4(ah[0], ahB + a0[kk]);
        ldmx4(ah[1], ahB + a1[kk]);
#pragma unroll
        for (int hf = 0; hf < 2; ++hf) {
            uint32_t bh[4][2];
#pragma unroll
            for (int ng = 0; ng < 2; ++ng) {
                uint32_t r[4];
                ldmx4(r, bhB + bo[2 * hf + ng][kk]);
                bh[2*ng][0] = r[0]; bh[2*ng][1] = r[1];
                bh[2*ng+1][0] = r[2]; bh[2*ng+1][1] = r[3];
            }
#pragma unroll
            for (int mt = 0; mt < 2; ++mt)
#pragma unroll
                for (int nt = 0; nt < 4; ++nt)
                    mma16816(acc[mt][4*hf + nt], ah[mt], bh[nt]);
        }
    }
}

// ---------------------------------------------------------------------------
// f16 GEMM (3-term), batched (z) + split-K (ks).
// 64x64 tile, 128 threads, BK=32, 3-stage ring, ONE sync/chunk, 4 CTAs/SM.
// ---------------------------------------------------------------------------
#define G_AH 0
#define G_AL 4096
#define G_BH 8192
#define G_BL 12288
#define STAGE_BYTES 16384
#define GEMM_SMEM   (3 * STAGE_BYTES + 128)   // 49280

__global__ void __launch_bounds__(128, 4) gemm_f16_kernel(
    const f16* __restrict__ Ah, const f16* __restrict__ Al,
    const f16* __restrict__ Wh, const f16* __restrict__ Wl,
    const float* __restrict__ bias,
    float* __restrict__ Cf, f16* __restrict__ Ch, f16* __restrict__ Cl,
    int N, int K, int relu, int ks, int pstr,
    int zsA, int zsW, int zsB, int zsC)
{
    extern __shared__ char smch[];
    const uint32_t base = (smem_u32(smch) + 127) & ~127u;

    const int z  = blockIdx.z / ks;
    const int kz = blockIdx.z % ks;
    const int Klocal = K / ks;
    const int kbase = kz * Klocal;

    Ah += (size_t)z * zsA;  Al += (size_t)z * zsA;
    Wh += (size_t)z * zsW;  Wl += (size_t)z * zsW;
    bias += (size_t)z * zsB;
    if (Cf) Cf += (size_t)z * zsC + (size_t)kz * pstr;
    if (Ch) { Ch += (size_t)z * zsC; Cl += (size_t)z * zsC; }

    const int tid  = threadIdx.x;
    const int lane = tid & 31;
    const int wid  = tid >> 5;
    const int wm   = wid & 1;
    const int wn   = wid >> 1;
    const int m0 = blockIdx.y * 64;
    const int n0 = blockIdx.x * 64;

    const f16* gsrc[8];
    uint32_t sdst[8];
#pragma unroll
    for (int it = 0; it < 8; ++it) {
        int c = tid + it * 128;
        int a = c >> 8;
        int idx = c & 255;
        int row = idx >> 2;
        int q   = idx & 3;
        const f16* p;
        if (a == 0)      p = Ah + (size_t)(m0 + row) * K;
        else if (a == 1) p = Al + (size_t)(m0 + row) * K;
        else if (a == 2) p = Wh + (size_t)(n0 + row) * K;
        else             p = Wl + (size_t)(n0 + row) * K;
        gsrc[it] = p + kbase + q * 8;
        sdst[it] = a * TILE64 + swz(row * 64 + q * 16);
    }

    const int nch = Klocal >> 5;
    auto issue = [&](int s) {
        uint32_t st = base + (s % 3) * STAGE_BYTES;
#pragma unroll
        for (int it = 0; it < 8; ++it)
            cp16(st + sdst[it], gsrc[it] + s * 32);
    };
    issue(0); CP_COMMIT;
    issue(1); CP_COMMIT;

    const int aRow = wm * 32 + (lane & 15);
    const int aCol = (lane >> 4) * 8;
    const int bRow = wn * 32 + (lane & 7) + ((lane >> 4) << 3);
    const int bCol = ((lane >> 3) & 1) * 8;
    uint32_t a0[2], a1[2], bo[2][2];
#pragma unroll
    for (int kk = 0; kk < 2; ++kk) {
        a0[kk] = swz(aRow * 64 + aCol * 2 + kk * 32);
        a1[kk] = swz((aRow + 16) * 64 + aCol * 2 + kk * 32);
#pragma unroll
        for (int ng = 0; ng < 2; ++ng)
            bo[ng][kk] = swz((bRow + ng * 16) * 64 + bCol * 2 + kk * 32);
    }

    float acc[2][4][4] = {};

    for (int s = 0; s < nch; ++s) {
        CP_WAIT1;
        __syncthreads();
        if (s + 2 < nch) issue(s + 2);
        CP_COMMIT;
        uint32_t st = base + (s % 3) * STAGE_BYTES;
        tile_mma44(st + G_AH, st + G_AL, st + G_BH, st + G_BL,
                   a0, a1, bo, acc);
    }

    const int addb = (kz == 0);
#pragma unroll
    for (int mt = 0; mt < 2; ++mt) {
        int r0 = m0 + wm * 32 + mt * 16 + (lane >> 2);
#pragma unroll
        for (int nt = 0; nt < 4; ++nt) {
            int col = n0 + wn * 32 + nt * 8 + (lane & 3) * 2;
            float b0 = addb ? bias[col] : 0.f, b1 = addb ? bias[col + 1] : 0.f;
            float v0 = acc[mt][nt][0] + b0, v1 = acc[mt][nt][1] + b1;
            float v2 = acc[mt][nt][2] + b0, v3 = acc[mt][nt][3] + b1;
            if (relu) {
                v0 = fmaxf(v0, 0.f); v1 = fmaxf(v1, 0.f);
                v2 = fmaxf(v2, 0.f); v3 = fmaxf(v3, 0.f);
            }
            if (Ch) {
                uint32_t hh, ll;
                split2(v0, v1, hh, ll);
                *(uint32_t*)&Ch[(size_t)r0 * N + col] = hh;
                *(uint32_t*)&Cl[(size_t)r0 * N + col] = ll;
                split2(v2, v3, hh, ll);
                *(uint32_t*)&Ch[(size_t)(r0 + 8) * N + col] = hh;
                *(uint32_t*)&Cl[(size_t)(r0 + 8) * N + col] = ll;
            } else {
                *(float2*)&Cf[(size_t)r0 * N + col]       = make_float2(v0, v1);
                *(float2*)&Cf[(size_t)(r0 + 8) * N + col] = make_float2(v2, v3);
            }
        }
    }
}

// ---------------------------------------------------------------------------
// Relation tensor (single-term fp16): out[b,i,:,:] = ((sub_b * W_bi) @ obj_b^T)
// A: fp32 load+scale -> fp16 (register double buffer); B: 3-stage cp.async.
// ---------------------------------------------------------------------------
#define RA_STAGE TILE_B     // Ah only
#define RB_STAGE TILE_B     // Bh only
#define REL_SMEM (2048 + 2 * RA_STAGE + 3 * RB_STAGE + 128)  // 43136

__global__ void __launch_bounds__(256, 2) final_tc_kernel(
    const float* __restrict__ sub, const f16* __restrict__ objh,
    const float* __restrict__ Wv, float* __restrict__ out)
{
    extern __shared__ char smch[];
    const uint32_t sb = (smem_u32(smch) + 127) & ~127u;
    float* ws = (float*)(smch + (sb - smem_u32(smch)));
    char* aPtr = (char*)ws + 2048;
    const uint32_t aBase = sb + 2048;
    const uint32_t bBase = aBase + 2 * RA_STAGE;

    const int i = blockIdx.x;
    const int b = blockIdx.y;
    const int tid  = threadIdx.x;
    const int lane = tid & 31;
    const int wid  = tid >> 5;
    const int wm   = wid & 3;
    const int wn   = wid >> 2;

    const float* wrow = Wv + (size_t)(b * SS + i) * DD;
    ws[tid]       = wrow[tid];
    ws[tid + 256] = wrow[tid + 256];

    const float* subB = sub + (size_t)b * SS * DD;
    const f16* ohB = objh + (size_t)b * SS * DD;

    // B cp.async: 2 x 16B per thread per stage (512 chunks total)
    const f16* bsrc[2];
    uint32_t bdst[2];
#pragma unroll
    for (int it = 0; it < 2; ++it) {
        int c = tid + it * 256;
        int row = c >> 2, q = c & 3;
        bsrc[it] = ohB + (size_t)row * DD + q * 8;
        bdst[it] = swz(row * 64 + q * 16);
    }
    int aLrow[4], aLc4[4];
#pragma unroll
    for (int it = 0; it < 4; ++it) {
        int idx = tid + it * 256;
        aLrow[it] = idx >> 3;
        aLc4[it]  = (idx & 7) << 2;
    }

    auto issueB = [&](int s) {
        uint32_t st = bBase + (s % 3) * RB_STAGE;
#pragma unroll
        for (int it = 0; it < 2; ++it)
            cp16(st + bdst[it], bsrc[it] + s * 32);
    };
    auto loadA = [&](int s, float4* r) {
#pragma unroll
        for (int it = 0; it < 4; ++it)
            r[it] = *(const float4*)&subB[(size_t)aLrow[it] * DD + s * 32 + aLc4[it]];
    };
    auto storeA = [&](int s, const float4* r) {
        char* dh = aPtr + (s & 1) * RA_STAGE;
        int kc = s * 32;
#pragma unroll
        for (int it = 0; it < 4; ++it) {
            float4 v = r[it];
            v.x *= ws[kc + aLc4[it]];     v.y *= ws[kc + aLc4[it] + 1];
            v.z *= ws[kc + aLc4[it] + 2]; v.w *= ws[kc + aLc4[it] + 3];
            uint32_t h0 = pack2(v.x, v.y);
            uint32_t h1 = pack2(v.z, v.w);
            uint32_t off = swz(aLrow[it] * 64 + aLc4[it] * 2);
            *(uint2*)(dh + off) = make_uint2(h0, h1);
        }
    };

    issueB(0); CP_COMMIT;
    issueB(1); CP_COMMIT;
    issueB(2); CP_COMMIT;
    __syncthreads();              // ws visible
    {
        float4 r0[4];
        loadA(0, r0);
        storeA(0, r0);
    }

    const int aRow = wm * 32 + (lane & 15);
    const int aCol = (lane >> 4) * 8;
    const int bRow = wn * 64 + (lane & 7) + ((lane >> 4) << 3);
    const int bCol = ((lane >> 3) & 1) * 8;
    uint32_t a0[2], a1[2], bo[4][2];
#pragma unroll
    for (int kk = 0; kk < 2; ++kk) {
        a0[kk] = swz(aRow * 64 + aCol * 2 + kk * 32);
        a1[kk] = swz((aRow + 16) * 64 + aCol * 2 + kk * 32);
#pragma unroll
        for (int ng = 0; ng < 4; ++ng)
            bo[ng][kk] = swz((bRow + ng * 16) * 64 + bCol * 2 + kk * 32);
    }

    float acc[2][8][4] = {};
    float4 pre[4];

    for (int s = 0; s < 16; ++s) {
        if (s + 1 < 16) loadA(s + 1, pre);
        CP_WAIT2;
        __syncthreads();
        uint32_t aB = aBase + (s & 1) * RA_STAGE;
        uint32_t bB = bBase + (s % 3) * RB_STAGE;
        tile_mma_rel(aB, bB, a0, a1, bo, acc);
        __syncthreads();
        if (s + 1 < 16) storeA(s + 1, pre);
        if (s + 3 < 16) issueB(s + 3);
        CP_COMMIT;
    }

    float* outB = out + (size_t)(b * SS + i) * SS * SS;
#pragma unroll
    for (int mt = 0; mt < 2; ++mt) {
        int r0 = wm * 32 + mt * 16 + (lane >> 2);
#pragma unroll
        for (int nt = 0; nt < 8; ++nt) {
            int col = wn * 64 + nt * 8 + (lane & 3) * 2;
            *(float2*)&outB[(size_t)r0 * SS + col] =
                make_float2(acc[mt][nt][0], acc[mt][nt][1]);
            *(float2*)&outB[(size_t)(r0 + 8) * SS + col] =
                make_float2(acc[mt][nt][2], acc[mt][nt][3]);
        }
    }
}

// ---------------------------------------------------------------------------
// Attention over axis L per (s, h); emits fp16 hi/lo.
// ---------------------------------------------------------------------------
__global__ void attn_kernel(const float* __restrict__ qkv,
                            f16* __restrict__ oh, f16* __restrict__ ol)
{
    const int s = blockIdx.x;
    const int h = blockIdx.y;
    const int t = threadIdx.x;  // 0..63

    __shared__ float qs[8][65], ks[8][65], vs[8][65];
    __shared__ float at[8][9];

#pragma unroll
    for (int l = 0; l < 8; ++l) {
        size_t base = (size_t)(l * SS + s) * (3 * DD) + h * HDD + t;
        qs[l][t] = qkv[base];
        ks[l][t] = qkv[base + DD];
        vs[l][t] = qkv[base + 2 * DD];
    }
    __syncthreads();

    const int l = t >> 3;
    const int m = t & 7;
    float sc = 0.0f;
#pragma unroll
    for (int d = 0; d < HDD; ++d) sc += qs[l][d] * ks[m][d];
    sc *= 0.125f;

    float mx = sc;
#pragma unroll
    for (int off = 1; off < 8; off <<= 1)
        mx = fmaxf(mx, __shfl_xor_sync(0xffffffffu, mx, off));
    float e = __expf(sc - mx);
    float sm = e;
#pragma unroll
    for (int off = 1; off < 8; off <<= 1)
        sm += __shfl_xor_sync(0xffffffffu, sm, off);
    at[l][m] = e / sm;
    __syncthreads();

    const int dg = (t & 7) * 8;
    float accv[8] = {};
#pragma unroll
    for (int mm = 0; mm < 8; ++mm) {
        float a = at[l][mm];
#pragma unroll
        for (int j = 0; j < 8; ++j)
            accv[j] = fmaf(a, vs[mm][dg + j], accv[j]);
    }
    size_t ob = (size_t)(l * SS + s) * DD + h * HDD + dg;
#pragma unroll
    for (int j = 0; j < 8; j += 2) {
        uint32_t hh, ll;
        split2(accv[j], accv[j + 1], hh, ll);
        *(uint32_t*)&oh[ob + j] = hh;
        *(uint32_t*)&ol[ob + j] = ll;
    }
}

// ---------------------------------------------------------------------------
// out = LayerNorm(a + sum_{p<np} P[p*pstr + .]); emits fp16 hi/lo if outh.
// ---------------------------------------------------------------------------
__global__ void add_ln_kernel(const float* __restrict__ a,
                              const float* __restrict__ P, int np, int pstr,
                              const float* __restrict__ gam, const float* __restrict__ bet,
                              float* __restrict__ out,
                              f16* __restrict__ outh, f16* __restrict__ outl)
{
    const int row = blockIdx.x;
    const int t = threadIdx.x;
    const size_t base = (size_t)row * DD;
    const int c = 2 * t;

    float v0 = a[base + c];
    float v1 = a[base + c + 1];
    for (int p = 0; p < np; ++p) {
        v0 += P[(size_t)p * pstr + base + c];
        v1 += P[(size_t)p * pstr + base + c + 1];
    }

    float s = v0 + v1;
    float q = v0 * v0 + v1 * v1;

    __shared__ float sred[16];
#pragma unroll
    for (int off = 16; off > 0; off >>= 1) {
        s += __shfl_xor_sync(0xffffffffu, s, off);
        q += __shfl_xor_sync(0xffffffffu, q, off);
    }
    if ((t & 31) == 0) { sred[t >> 5] = s; sred[(t >> 5) + 8] = q; }
    __syncthreads();
    if (t < 32) {
        float ss = (t < 8) ? sred[t] : 0.0f;
        float qq = (t < 8) ? sred[t + 8] : 0.0f;
#pragma unroll
        for (int off = 4; off > 0; off >>= 1) {
            ss += __shfl_xor_sync(0xffffffffu, ss, off);
            qq += __shfl_xor_sync(0xffffffffu, qq, off);
        }
        if (t == 0) { sred[0] = ss; sred[1] = qq; }
    }
    __syncthreads();

    const float mean = sred[0] * (1.0f / 512.0f);
    const float var  = sred[1] * (1.0f / 512.0f) - mean * mean;
    const float rstd = rsqrtf(var + 1e-5f);

    float y0 = (v0 - mean) * rstd * gam[c]     + bet[c];
    float y1 = (v1 - mean) * rstd * gam[c + 1] + bet[c + 1];
    *(float2*)&out[base + c] = make_float2(y0, y1);
    if (outh) {
        uint32_t hh, ll;
        split2(y0, y1, hh, ll);
        *(uint32_t*)&outh[base + c] = hh;
        *(uint32_t*)&outl[base + c] = ll;
    }
}

// ---------------------------------------------------------------------------
// Fused splitter: 8 segments of fp32 -> fp16 hi/lo (one launch).
// ---------------------------------------------------------------------------
struct SplitArgs {
    const float* src[8];
    f16* dh[8];
    f16* dl[8];
    int bstart[9];
};

__global__ void fused_split_kernel(SplitArgs sa)
{
    int blk = blockIdx.x;
    int seg = 0;
#pragma unroll
    for (int s = 1; s < 8; ++s) seg += (blk >= sa.bstart[s]);
    int idx = (blk - sa.bstart[seg]) * 256 + threadIdx.x;
    float4 x = ((const float4*)sa.src[seg])[idx];
    uint32_t h0, h1, l0, l1;
    split2(x.x, x.y, h0, l0);
    split2(x.z, x.w, h1, l1);
    ((uint2*)sa.dh[seg])[idx] = make_uint2(h0, h1);
    ((uint2*)sa.dl[seg])[idx] = make_uint2(l0, l1);
}

// ---------------------------------------------------------------------------
// Consumes 4 mlp2 batch slabs: obj = P1 -> fp16 (hi only); Wv = P2 * P3.
// (sub = P0 is consumed directly by final_tc_kernel.)
// ---------------------------------------------------------------------------
__global__ void mul_split_kernel(const float* __restrict__ P,
                                 float* __restrict__ Wv,
                                 f16* __restrict__ oh)
{
    int i = blockIdx.x * blockDim.x + threadIdx.x;   // float4 index
    const float4* P4 = (const float4*)P;
    const int S4 = PSTR / 4;

    float4 o = P4[i + S4];
    ((uint2*)oh)[i] = make_uint2(pack2(o.x, o.y), pack2(o.z, o.w));

    float4 a = P4[i + 2 * S4];
    float4 b = P4[i + 3 * S4];
    ((float4*)Wv)[i] = make_float4(a.x * b.x, a.y * b.y, a.z * b.z, a.w * b.w);
}

// ---------------------------------------------------------------------------
extern "C" void kernel_launch(void* const* d_in, const int* in_sizes, int n_in,
                              void* d_out, int out_size)
{
    const float* x   = (const float*)d_in[0];
    const float* aiw = (const float*)d_in[1];
    const float* aib = (const float*)d_in[2];
    const float* aow = (const float*)d_in[3];
    const float* aob = (const float*)d_in[4];
    const float* l1w = (const float*)d_in[5];
    const float* l1b = (const float*)d_in[6];
    const float* l2w = (const float*)d_in[7];
    const float* l2b = (const float*)d_in[8];
    const float* f1w = (const float*)d_in[9];
    const float* f1b = (const float*)d_in[10];
    const float* f2w = (const float*)d_in[11];
    const float* f2b = (const float*)d_in[12];
    const float* flw = (const float*)d_in[13];
    const float* flb = (const float*)d_in[14];
    const float* w0  = (const float*)d_in[15];
    const float* b0  = (const float*)d_in[16];
    const float* w1  = (const float*)d_in[17];
    const float* b1  = (const float*)d_in[18];
    const float* w2  = (const float*)d_in[19];
    const float* b2  = (const float*)d_in[20];
    float* out = (float*)d_out;

    f16 *wh, *wl, *s0h, *s0l, *s1h, *s1l;
    float *h, *qkv, *part, *Wv;
    cudaGetSymbolAddress((void**)&wh,   g_wh);
    cudaGetSymbolAddress((void**)&wl,   g_wl);
    cudaGetSymbolAddress((void**)&s0h,  g_s0h);
    cudaGetSymbolAddress((void**)&s0l,  g_s0l);
    cudaGetSymbolAddress((void**)&s1h,  g_s1h);
    cudaGetSymbolAddress((void**)&s1l,  g_s1l);
    cudaGetSymbolAddress((void**)&h,    g_h);
    cudaGetSymbolAddress((void**)&qkv,  g_qkv);
    cudaGetSymbolAddress((void**)&part, g_part);
    cudaGetSymbolAddress((void**)&Wv,   g_Wv);

    cudaFuncSetAttribute(gemm_f16_kernel,
                         cudaFuncAttributeMaxDynamicSharedMemorySize, GEMM_SMEM);
    cudaFuncSetAttribute(final_tc_kernel,
                         cudaFuncAttributeMaxDynamicSharedMemorySize, REL_SMEM);

    // ---- launch 1: all splits fused (weights + x) ----
    {
        SplitArgs sa;
        sa.src[0] = aiw; sa.dh[0] = wh + OFF_AIW; sa.dl[0] = wl + OFF_AIW;
        sa.src[1] = aow; sa.dh[1] = wh + OFF_AOW; sa.dl[1] = wl + OFF_AOW;
        sa.src[2] = f1w; sa.dh[2] = wh + OFF_F1W; sa.dl[2] = wl + OFF_F1W;
        sa.src[3] = f2w; sa.dh[3] = wh + OFF_F2W; sa.dl[3] = wl + OFF_F2W;
        sa.src[4] = w0;  sa.dh[4] = wh + OFF_W0;  sa.dl[4] = wl + OFF_W0;
        sa.src[5] = w1;  sa.dh[5] = wh + OFF_W1;  sa.dl[5] = wl + OFF_W1;
        sa.src[6] = w2;  sa.dh[6] = wh + OFF_W2;  sa.dl[6] = wl + OFF_W2;
        sa.src[7] = x;   sa.dh[7] = s0h;          sa.dl[7] = s0l;
        int sizes[8] = {2359296, 786432, 3145728, 3145728,
                        1048576, 1048576, 1048576, 524288};
        int acc = 0;
        for (int s = 0; s < 8; ++s) { sa.bstart[s] = acc; acc += sizes[s] / 1024; }
        sa.bstart[8] = acc;
        fused_split_kernel<<<acc, 256>>>(sa);
    }

    // ---- encoder: 3 post-norm layers ----
    for (int i = 0; i < 3; ++i) {
        // qkv: grid (24,16,1)=384 CTAs, 16 chunks each
        gemm_f16_kernel<<<dim3(24, 16, 1), 128, GEMM_SMEM>>>(
            s0h, s0l, wh + OFF_AIW + (size_t)i * 786432, wl + OFF_AIW + (size_t)i * 786432,
            aib + i * 1536, qkv, nullptr, nullptr, 1536, 512, 0, 1, 0, 0, 0, 0, 0);

        attn_kernel<<<dim3(SS, HH), 64>>>(qkv, s1h, s1l);

        // attn-out, split-K4: grid (8,16,4)=512
        gemm_f16_kernel<<<dim3(8, 16, 4), 128, GEMM_SMEM>>>(
            s1h, s1l, wh + OFF_AOW + (size_t)i * 262144, wl + OFF_AOW + (size_t)i * 262144,
            aob + i * 512, part, nullptr, nullptr, 512, 512, 0, 4, PSTR, 0, 0, 0, 0);

        add_ln_kernel<<<NT, 256>>>((i == 0) ? x : h, part, 4, PSTR,
                                   l1w + i * 512, l1b + i * 512, h, s0h, s0l);

        // ff1 = relu(...) -> fp16 splits : grid (32,16)=512
        gemm_f16_kernel<<<dim3(32, 16, 1), 128, GEMM_SMEM>>>(
            s0h, s0l, wh + OFF_F1W + (size_t)i * 1048576, wl + OFF_F1W + (size_t)i * 1048576,
            f1b + i * 2048, nullptr, s1h, s1l, 2048, 512, 1, 1, 0, 0, 0, 0, 0);

        // ff2, split-K4 : grid (8,16,4)=512, 16 chunks
        gemm_f16_kernel<<<dim3(8, 16, 4), 128, GEMM_SMEM>>>(
            s1h, s1l, wh + OFF_F2W + (size_t)i * 1048576, wl + OFF_F2W + (size_t)i * 1048576,
            f2b + i * 512, part, nullptr, nullptr, 512, 2048, 0, 4, PSTR, 0, 0, 0, 0);

        add_ln_kernel<<<NT, 256>>>(h, part, 4, PSTR,
                                   l2w + i * 512, l2b + i * 512, h, s0h, s0l);
    }

    // final encoder LN
    add_ln_kernel<<<NT, 256>>>(h, (const float*)nullptr, 0, 0, flw, flb, h, s0h, s0l);

    // ---- 4 projection MLPs, batched via blockIdx.z ----
    const int ZW = 262144, ZB = 512, ZC = NT * DD;
    gemm_f16_kernel<<<dim3(8, 16, 4), 128, GEMM_SMEM>>>(
        s0h, s0l, wh + OFF_W0, wl + OFF_W0, b0, nullptr, s1h, s1l,
        512, 512, 1, 1, 0, 0, ZW, ZB, ZC);
    gemm_f16_kernel<<<dim3(8, 16, 4), 128, GEMM_SMEM>>>(
        s1h, s1l, wh + OFF_W1, wl + OFF_W1, b1, nullptr, s0h, s0l,
        512, 512, 1, 1, 0, ZC, ZW, ZB, ZC);
    // mlp2: 4 z-batched fp32 outputs -> part slabs [sub|obj|vsub|vobj]
    gemm_f16_kernel<<<dim3(8, 16, 4), 128, GEMM_SMEM>>>(
        s0h, s0l, wh + OFF_W2, wl + OFF_W2, b2, part, nullptr, nullptr,
        512, 512, 0, 1, 0, ZC, ZW, ZB, PSTR);

    // obj -> fp16 (hi); Wv = vsub*vobj (sub used in place from part)
    mul_split_kernel<<<512, 256>>>(part, Wv, s1h);

    // relation tensor: (8, 128, 128, 128), single-term fp16
    final_tc_kernel<<<dim3(SS, LL), 256, REL_SMEM>>>(part, s1h, Wv, out);
}